// round 1
// baseline (speedup 1.0000x reference)
#include <cuda_runtime.h>
#include <math.h>

// Problem shape (fixed by the dataset)
#define NB 16
#define TT 1024
#define TS 1024
#define HH 1024
#define OO 1024

// Scratch (allowed: __device__ globals, no allocation)
__device__ float g_hs_proj[(size_t)NB * TS * HH];   // 64 MB
__device__ float g_score [(size_t)NB * TT * TS];    // 64 MB (reused in-place for softmax)
__device__ float g_c     [(size_t)NB * TT * HH];    // 64 MB
__device__ int   g_lens  [NB];

// ---------------------------------------------------------------------------
// lens[b] = count of source[b,s] != 0
// ---------------------------------------------------------------------------
__global__ void lens_kernel(const int* __restrict__ source, int* __restrict__ lens)
{
    int b = blockIdx.x;
    int tid = threadIdx.x;
    int cnt = 0;
    for (int s = tid; s < TS; s += blockDim.x)
        cnt += (source[(size_t)b * TS + s] != 0);
    __shared__ int red[256];
    red[tid] = cnt;
    __syncthreads();
    for (int s = 128; s > 0; s >>= 1) {
        if (tid < s) red[tid] += red[tid + s];
        __syncthreads();
    }
    if (tid == 0) lens[b] = red[0];
}

// ---------------------------------------------------------------------------
// Generic 128x128x8 SGEMM, 256 threads, 8x8 per thread.
// C[M,N] = A[M,K] * op(B)  where op(B) = B[K,N] (NN) or B[N,K]^T (NT).
// Batched via blockIdx.z with element strides sA/sB/sC.
// All dims assumed multiples of 128 / 8 (true for this problem).
// ---------------------------------------------------------------------------
template <bool TRANSB>
__global__ __launch_bounds__(256)
void sgemm128(const float* __restrict__ A, const float* __restrict__ Bm,
              float* __restrict__ C, int M, int N, int K,
              size_t sA, size_t sB, size_t sC)
{
    A  += (size_t)blockIdx.z * sA;
    Bm += (size_t)blockIdx.z * sB;
    C  += (size_t)blockIdx.z * sC;

    const int bm = blockIdx.y * 128;
    const int bn = blockIdx.x * 128;

    __shared__ float As[8][128];
    __shared__ float Bs[8][128];

    const int tid = threadIdx.x;
    const int lr = tid >> 1;            // 0..127 (row for A / B-NT loads)
    const int lc = (tid & 1) * 4;       // 0 or 4 (k offset)
    const int br = tid >> 5;            // 0..7   (k row for B-NN loads)
    const int bc = (tid & 31) * 4;      // 0..124 (n offset)
    const int tr = (tid >> 4) * 8;      // C row base within tile
    const int tc = (tid & 15) * 8;      // C col base within tile

    float acc[8][8];
#pragma unroll
    for (int i = 0; i < 8; i++)
#pragma unroll
        for (int j = 0; j < 8; j++) acc[i][j] = 0.f;

    for (int k0 = 0; k0 < K; k0 += 8) {
        float4 av = *(const float4*)(A + (size_t)(bm + lr) * K + k0 + lc);
        As[lc + 0][lr] = av.x; As[lc + 1][lr] = av.y;
        As[lc + 2][lr] = av.z; As[lc + 3][lr] = av.w;
        if (TRANSB) {
            float4 bv = *(const float4*)(Bm + (size_t)(bn + lr) * K + k0 + lc);
            Bs[lc + 0][lr] = bv.x; Bs[lc + 1][lr] = bv.y;
            Bs[lc + 2][lr] = bv.z; Bs[lc + 3][lr] = bv.w;
        } else {
            float4 bv = *(const float4*)(Bm + (size_t)(k0 + br) * N + bn + bc);
            *(float4*)&Bs[br][bc] = bv;
        }
        __syncthreads();
#pragma unroll
        for (int k = 0; k < 8; k++) {
            float4 a0 = *(const float4*)&As[k][tr];
            float4 a1 = *(const float4*)&As[k][tr + 4];
            float4 b0 = *(const float4*)&Bs[k][tc];
            float4 b1 = *(const float4*)&Bs[k][tc + 4];
            float ar[8]  = {a0.x, a0.y, a0.z, a0.w, a1.x, a1.y, a1.z, a1.w};
            float brg[8] = {b0.x, b0.y, b0.z, b0.w, b1.x, b1.y, b1.z, b1.w};
#pragma unroll
            for (int i = 0; i < 8; i++)
#pragma unroll
                for (int j = 0; j < 8; j++)
                    acc[i][j] = fmaf(ar[i], brg[j], acc[i][j]);
        }
        __syncthreads();
    }

#pragma unroll
    for (int i = 0; i < 8; i++) {
        float4 o0 = {acc[i][0], acc[i][1], acc[i][2], acc[i][3]};
        float4 o1 = {acc[i][4], acc[i][5], acc[i][6], acc[i][7]};
        float* crow = C + (size_t)(bm + tr + i) * N + bn + tc;
        *(float4*)(crow)     = o0;
        *(float4*)(crow + 4) = o1;
    }
}

// ---------------------------------------------------------------------------
// Masked softmax over the last dim (row length TS = 1024), in-place.
// Matches reference: max over FULL row first, then e = exp(x-max)*mask,
// a = e / sum(e).   rows = NB*TT, one block (256 thr) per row.
// ---------------------------------------------------------------------------
__global__ void softmax_kernel(float* __restrict__ score, const int* __restrict__ lens)
{
    int row = blockIdx.x;              // 0 .. NB*TT-1
    int b = row >> 10;                 // row / TT
    int tid = threadIdx.x;
    float* r = score + (size_t)row * TS;
    int len = lens[b];

    float4 x = ((const float4*)r)[tid];          // 256 threads * 4 = 1024
    float m = fmaxf(fmaxf(x.x, x.y), fmaxf(x.z, x.w));

    __shared__ float red[256];
    red[tid] = m;
    __syncthreads();
    for (int s = 128; s > 0; s >>= 1) {
        if (tid < s) red[tid] = fmaxf(red[tid], red[tid + s]);
        __syncthreads();
    }
    float rowmax = red[0];
    __syncthreads();

    int base = tid * 4;
    float e0 = (base + 0 < len) ? expf(x.x - rowmax) : 0.f;
    float e1 = (base + 1 < len) ? expf(x.y - rowmax) : 0.f;
    float e2 = (base + 2 < len) ? expf(x.z - rowmax) : 0.f;
    float e3 = (base + 3 < len) ? expf(x.w - rowmax) : 0.f;

    red[tid] = e0 + e1 + e2 + e3;
    __syncthreads();
    for (int s = 128; s > 0; s >>= 1) {
        if (tid < s) red[tid] += red[tid + s];
        __syncthreads();
    }
    float inv = 1.0f / red[0];

    float4 o = {e0 * inv, e1 * inv, e2 * inv, e3 * inv};
    ((float4*)r)[tid] = o;
}

// ---------------------------------------------------------------------------
// Fused concat GEMM + bias + tanh:
//   out[M,N] = tanh( [A1 | A2] (M x 2048)  @  Wc (2048 x N)  + bias )
// A1 = c, A2 = ht, each M x 1024 row-major. Same tiling as sgemm128.
// ---------------------------------------------------------------------------
__global__ __launch_bounds__(256)
void sgemm_concat_tanh(const float* __restrict__ A1, const float* __restrict__ A2,
                       const float* __restrict__ Wc, const float* __restrict__ bias,
                       float* __restrict__ C, int M, int N)
{
    const int bm = blockIdx.y * 128;
    const int bn = blockIdx.x * 128;

    __shared__ float As[8][128];
    __shared__ float Bs[8][128];

    const int tid = threadIdx.x;
    const int lr = tid >> 1;
    const int lc = (tid & 1) * 4;
    const int br = tid >> 5;
    const int bc = (tid & 31) * 4;
    const int tr = (tid >> 4) * 8;
    const int tc = (tid & 15) * 8;

    float acc[8][8];
#pragma unroll
    for (int i = 0; i < 8; i++)
#pragma unroll
        for (int j = 0; j < 8; j++) acc[i][j] = 0.f;

    for (int k0 = 0; k0 < 2 * HH; k0 += 8) {
        const float* Asrc = (k0 < HH) ? A1 : A2;
        int kk = (k0 < HH) ? k0 : (k0 - HH);
        float4 av = *(const float4*)(Asrc + (size_t)(bm + lr) * HH + kk + lc);
        As[lc + 0][lr] = av.x; As[lc + 1][lr] = av.y;
        As[lc + 2][lr] = av.z; As[lc + 3][lr] = av.w;
        float4 bv = *(const float4*)(Wc + (size_t)(k0 + br) * N + bn + bc);
        *(float4*)&Bs[br][bc] = bv;
        __syncthreads();
#pragma unroll
        for (int k = 0; k < 8; k++) {
            float4 a0 = *(const float4*)&As[k][tr];
            float4 a1 = *(const float4*)&As[k][tr + 4];
            float4 b0 = *(const float4*)&Bs[k][tc];
            float4 b1 = *(const float4*)&Bs[k][tc + 4];
            float ar[8]  = {a0.x, a0.y, a0.z, a0.w, a1.x, a1.y, a1.z, a1.w};
            float brg[8] = {b0.x, b0.y, b0.z, b0.w, b1.x, b1.y, b1.z, b1.w};
#pragma unroll
            for (int i = 0; i < 8; i++)
#pragma unroll
                for (int j = 0; j < 8; j++)
                    acc[i][j] = fmaf(ar[i], brg[j], acc[i][j]);
        }
        __syncthreads();
    }

#pragma unroll
    for (int i = 0; i < 8; i++) {
        float4 o0, o1;
        o0.x = tanhf(acc[i][0] + bias[bn + tc + 0]);
        o0.y = tanhf(acc[i][1] + bias[bn + tc + 1]);
        o0.z = tanhf(acc[i][2] + bias[bn + tc + 2]);
        o0.w = tanhf(acc[i][3] + bias[bn + tc + 3]);
        o1.x = tanhf(acc[i][4] + bias[bn + tc + 4]);
        o1.y = tanhf(acc[i][5] + bias[bn + tc + 5]);
        o1.z = tanhf(acc[i][6] + bias[bn + tc + 6]);
        o1.w = tanhf(acc[i][7] + bias[bn + tc + 7]);
        float* crow = C + (size_t)(bm + tr + i) * N + bn + tc;
        *(float4*)(crow)     = o0;
        *(float4*)(crow + 4) = o1;
    }
}

// ---------------------------------------------------------------------------
// Host launch
// ---------------------------------------------------------------------------
extern "C" void kernel_launch(void* const* d_in, const int* in_sizes, int n_in,
                              void* d_out, int out_size)
{
    const float* ht     = (const float*)d_in[0];  // [16,1024,1024]
    const float* hs     = (const float*)d_in[1];  // [16,1024,1024]
    const float* W_a    = (const float*)d_in[2];  // [1024,1024]
    const float* W_c    = (const float*)d_in[3];  // [2048,1024]
    const float* bias   = (const float*)d_in[4];  // [1024]
    const int*   source = (const int*)d_in[5];    // [16,1024]
    float* out = (float*)d_out;                   // [16,1024,1024]

    float *hs_proj, *score, *c;
    int* lens;
    cudaGetSymbolAddress((void**)&hs_proj, g_hs_proj);
    cudaGetSymbolAddress((void**)&score,   g_score);
    cudaGetSymbolAddress((void**)&c,       g_c);
    cudaGetSymbolAddress((void**)&lens,    g_lens);

    // 1) sequence lengths
    lens_kernel<<<NB, 256>>>(source, lens);

    // 2) hs_proj = hs @ W_a      (flattened: 16384 x 1024 x 1024, NN)
    {
        dim3 g(HH / 128, (NB * TS) / 128, 1);
        sgemm128<false><<<g, 256>>>(hs, W_a, hs_proj,
                                    NB * TS, HH, HH, 0, 0, 0);
    }

    // 3) score[b] = ht[b] @ hs_proj[b]^T   (batched NT, 1024^3 x 16)
    {
        dim3 g(TS / 128, TT / 128, NB);
        sgemm128<true><<<g, 256>>>(ht, hs_proj, score,
                                   TT, TS, HH,
                                   (size_t)TT * HH, (size_t)TS * HH, (size_t)TT * TS);
    }

    // 4) masked softmax (in-place on score)
    softmax_kernel<<<NB * TT, 256>>>(score, lens);

    // 5) c[b] = a[b] @ hs[b]     (batched NN, 1024^3 x 16)
    {
        dim3 g(HH / 128, TT / 128, NB);
        sgemm128<false><<<g, 256>>>(score, hs, c,
                                    TT, HH, TS,
                                    (size_t)TT * TS, (size_t)TS * HH, (size_t)TT * HH);
    }

    // 6) out = tanh([c | ht] @ W_c + b)   (16384 x 1024 x 2048, fused epilogue)
    {
        dim3 g(OO / 128, (NB * TT) / 128, 1);
        sgemm_concat_tanh<<<g, 256>>>(c, ht, W_c, bias, out, NB * TT, OO);
    }
}

// round 4
// speedup vs baseline: 1.5377x; 1.5377x over previous
#include <cuda_runtime.h>
#include <math.h>
#include <cstdint>

// Problem shape (fixed)
#define NB 16
#define TT 1024
#define TS 1024
#define HH 1024
#define OO 1024

// ---------------------------------------------------------------------------
// Scratch (device globals; no allocation). hi/lo = exact tf32 split pairs.
// ---------------------------------------------------------------------------
__device__ float g_hs_hi  [(size_t)NB * TS * HH];
__device__ float g_hs_lo  [(size_t)NB * TS * HH];
__device__ float g_ht_hi  [(size_t)NB * TT * HH];
__device__ float g_ht_lo  [(size_t)NB * TT * HH];
__device__ float g_proj_hi[(size_t)NB * TS * HH];
__device__ float g_proj_lo[(size_t)NB * TS * HH];
__device__ float g_score  [(size_t)NB * TT * TS];   // scores, then a_hi in-place
__device__ float g_a_lo   [(size_t)NB * TT * TS];
__device__ float g_hsT_hi [(size_t)NB * HH * TS];
__device__ float g_hsT_lo [(size_t)NB * HH * TS];
__device__ float g_c_hi   [(size_t)NB * TT * HH];
__device__ float g_c_lo   [(size_t)NB * TT * HH];
__device__ float g_WaT_hi [(size_t)HH * HH];
__device__ float g_WaT_lo [(size_t)HH * HH];
__device__ float g_WcT_hi [(size_t)OO * 2 * HH];    // [O=1024][K=2048]
__device__ float g_WcT_lo [(size_t)OO * 2 * HH];
__device__ int   g_lens   [NB];

// ---------------------------------------------------------------------------
// Helpers / PTX (base ISA only — works through compute_103)
// ---------------------------------------------------------------------------
__device__ __forceinline__ uint32_t smem_u32(const void* p) {
    uint32_t a;
    asm("{ .reg .u64 t; cvta.to.shared.u64 t, %1; cvt.u32.u64 %0, t; }"
        : "=r"(a) : "l"(p));
    return a;
}
__device__ __forceinline__ float rna_tf32(float x) {
    uint32_t r; asm("cvt.rna.tf32.f32 %0, %1;" : "=r"(r) : "f"(x));
    return __uint_as_float(r);
}

#define CPASYNC16(saddr, gaddr) \
    asm volatile("cp.async.cg.shared.global [%0], [%1], 16;" :: "r"(saddr), "l"(gaddr))

__device__ __forceinline__ void ldm4(uint32_t* r, uint32_t addr) {
    asm volatile("ldmatrix.sync.aligned.m8n8.x4.shared.b16 {%0,%1,%2,%3}, [%4];"
                 : "=r"(r[0]), "=r"(r[1]), "=r"(r[2]), "=r"(r[3]) : "r"(addr));
}
__device__ __forceinline__ void mma8(float* c, const uint32_t* a, const uint32_t* b) {
    asm volatile(
        "mma.sync.aligned.m16n8k8.row.col.f32.tf32.tf32.f32 "
        "{%0,%1,%2,%3}, {%4,%5,%6,%7}, {%8,%9}, {%0,%1,%2,%3};"
        : "+f"(c[0]), "+f"(c[1]), "+f"(c[2]), "+f"(c[3])
        : "r"(a[0]), "r"(a[1]), "r"(a[2]), "r"(a[3]), "r"(b[0]), "r"(b[1]));
}

// Per-segment operand pointers (K = NSEG * 1024, segment k-width 1024)
struct SegArgs {
    const float* a[6];
    const float* b[6];
};

// ---------------------------------------------------------------------------
// tf32 mma.sync GEMM: C[M,N] = sum_seg A_seg[M,1024] * B_seg[N,1024]^T
// CTA tile 128x128, kstep 32, 256 thr = 8 warps (2x4), warp tile 64x32.
// 4-stage cp.async pipeline, SW128 xor swizzle, ldmatrix fragments.
// lda fixed 1024 for all A segments. ldb uniform per call.
// EPI: 0 plain, 2 tanh(x+bias), 3 split -> C(hi), C2(lo).
// ---------------------------------------------------------------------------
static const int NSTG = 4;
static const int STAGE = 32768;                  // 16KB A + 16KB B
static const int GEMM_SMEM = 1024 + NSTG * STAGE;

template <int EPI, int NSEG>
__global__ __launch_bounds__(256, 1)
void gemm_mma(const SegArgs segs, float* __restrict__ C, float* __restrict__ C2,
              const float* __restrict__ bias, int ldb, int ldc,
              long long sA, long long sB, long long sC)
{
    extern __shared__ char smem[];
    const uint32_t data = (smem_u32(smem) + 1023) & ~1023u;

    const int tid  = threadIdx.x;
    const int lane = tid & 31;
    const int warp = tid >> 5;
    const int wm = (warp >> 2) << 6;     // 0 or 64
    const int wn = (warp & 3) << 5;      // 0,32,64,96
    const int bm = blockIdx.y << 7;
    const int bn = blockIdx.x << 7;

    const long long zA = (long long)blockIdx.z * sA;
    const long long zB = (long long)blockIdx.z * sB;
    float* Cb  = C + (size_t)blockIdx.z * sC;
    float* C2b = (EPI == 3) ? C2 + (size_t)blockIdx.z * sC : (float*)0;

    const int KT = NSEG * 32;            // k-steps of 32

    auto fill = [&](int kt, int s) {
        const int seg = kt >> 5;
        const int ka  = (kt & 31) << 5;
        const float* Ap = segs.a[seg] + zA;
        const float* Bp = segs.b[seg] + zB;
        const uint32_t sa = data + s * STAGE;
        const uint32_t sb = sa + 16384;
#pragma unroll
        for (int i = 0; i < 4; i++) {
            int c = tid + (i << 8);
            int row = c >> 3, ch = c & 7;
            const float* g = Ap + (size_t)(bm + row) * 1024 + ka + (ch << 2);
            CPASYNC16(sa + (row << 7) + (((ch ^ (row & 7))) << 4), g);
        }
#pragma unroll
        for (int i = 0; i < 4; i++) {
            int c = tid + (i << 8);
            int row = c >> 3, ch = c & 7;
            const float* g = Bp + (size_t)(bn + row) * ldb + ka + (ch << 2);
            CPASYNC16(sb + (row << 7) + (((ch ^ (row & 7))) << 4), g);
        }
    };

#pragma unroll
    for (int s = 0; s < NSTG - 1; s++) {
        fill(s, s);
        asm volatile("cp.async.commit_group;" ::: "memory");
    }

    float acc[4][4][4];
#pragma unroll
    for (int a = 0; a < 4; a++)
#pragma unroll
        for (int b = 0; b < 4; b++)
#pragma unroll
            for (int c = 0; c < 4; c++) acc[a][b][c] = 0.f;

    const int r8 = lane & 7;
    const int mh = lane >> 3;

    for (int kt = 0; kt < KT; kt++) {
        asm volatile("cp.async.wait_group 2;" ::: "memory");
        __syncthreads();

        int nf = kt + NSTG - 1;
        if (nf < KT) fill(nf, nf & (NSTG - 1));
        asm volatile("cp.async.commit_group;" ::: "memory");

        const uint32_t Ab = data + (kt & (NSTG - 1)) * STAGE;
        const uint32_t Bs = Ab + 16384;
#pragma unroll
        for (int k8 = 0; k8 < 4; k8++) {
            uint32_t af[4][4], bf[2][4];
#pragma unroll
            for (int mt = 0; mt < 4; mt++) {
                int arow = wm + mt * 16 + r8 + ((mh & 1) << 3);
                int achk = 2 * k8 + (mh >> 1);
                ldm4(af[mt], Ab + (arow << 7) + (((achk ^ (arow & 7))) << 4));
            }
#pragma unroll
            for (int p = 0; p < 2; p++) {
                int brow = wn + (p << 4) + r8 + ((mh >> 1) << 3);
                int bchk = 2 * k8 + (mh & 1);
                ldm4(bf[p], Bs + (brow << 7) + (((bchk ^ (brow & 7))) << 4));
            }
#pragma unroll
            for (int mt = 0; mt < 4; mt++)
#pragma unroll
                for (int nt = 0; nt < 4; nt++)
                    mma8(acc[mt][nt], af[mt], &bf[nt >> 1][(nt & 1) << 1]);
        }
    }

    const int row0 = bm + wm + (lane >> 2);
    const int col0 = bn + wn + ((lane & 3) << 1);
#pragma unroll
    for (int mt = 0; mt < 4; mt++) {
#pragma unroll
        for (int nt = 0; nt < 4; nt++) {
            int col = col0 + nt * 8;
#pragma unroll
            for (int h = 0; h < 2; h++) {
                int row = row0 + mt * 16 + h * 8;
                float v0 = acc[mt][nt][2 * h + 0];
                float v1 = acc[mt][nt][2 * h + 1];
                float* dst = Cb + (size_t)row * ldc + col;
                if (EPI == 0) {
                    float2 o = {v0, v1};
                    *(float2*)dst = o;
                } else if (EPI == 2) {
                    float2 o = {tanhf(v0 + bias[col]), tanhf(v1 + bias[col + 1])};
                    *(float2*)dst = o;
                } else {  // split
                    float h0 = rna_tf32(v0), h1 = rna_tf32(v1);
                    float2 oh = {h0, h1};
                    float2 ol = {rna_tf32(v0 - h0), rna_tf32(v1 - h1)};
                    *(float2*)dst = oh;
                    *(float2*)(C2b + (size_t)row * ldc + col) = ol;
                }
            }
        }
    }
}

// ---------------------------------------------------------------------------
// Preprocessing kernels
// ---------------------------------------------------------------------------
__global__ void split_pair(const float* __restrict__ in, float* __restrict__ hi,
                           float* __restrict__ lo, size_t n4)
{
    size_t i  = (size_t)blockIdx.x * blockDim.x + threadIdx.x;
    size_t st = (size_t)gridDim.x * blockDim.x;
    for (; i < n4; i += st) {
        float4 v = ((const float4*)in)[i];
        float4 h, l;
        h.x = rna_tf32(v.x); l.x = rna_tf32(v.x - h.x);
        h.y = rna_tf32(v.y); l.y = rna_tf32(v.y - h.y);
        h.z = rna_tf32(v.z); l.z = rna_tf32(v.z - h.z);
        h.w = rna_tf32(v.w); l.w = rna_tf32(v.w - h.w);
        ((float4*)hi)[i] = h;
        ((float4*)lo)[i] = l;
    }
}

// dst_{hi,lo}[c][r] = split(src[r][c]), batched over z
__global__ void transpose_split(const float* __restrict__ src, float* __restrict__ hi,
                                float* __restrict__ lo, int R, int C)
{
    __shared__ float t[32][33];
    size_t boff = (size_t)blockIdx.z * R * C;
    src += boff; hi += boff; lo += boff;
    int r0 = blockIdx.y << 5, c0 = blockIdx.x << 5;
    int tx = threadIdx.x, ty = threadIdx.y;
#pragma unroll
    for (int i = 0; i < 32; i += 8)
        t[ty + i][tx] = src[(size_t)(r0 + ty + i) * C + c0 + tx];
    __syncthreads();
#pragma unroll
    for (int i = 0; i < 32; i += 8) {
        float v = t[tx][ty + i];
        float h = rna_tf32(v), l = rna_tf32(v - h);
        size_t idx = (size_t)(c0 + ty + i) * R + r0 + tx;
        hi[idx] = h;
        lo[idx] = l;
    }
}

__global__ void lens_kernel(const int* __restrict__ source, int* __restrict__ lens)
{
    int b = blockIdx.x, tid = threadIdx.x;
    int cnt = 0;
    for (int s = tid; s < TS; s += blockDim.x)
        cnt += (source[(size_t)b * TS + s] != 0);
    __shared__ int red[256];
    red[tid] = cnt;
    __syncthreads();
    for (int s = 128; s > 0; s >>= 1) {
        if (tid < s) red[tid] += red[tid + s];
        __syncthreads();
    }
    if (tid == 0) lens[b] = red[0];
}

// masked softmax; writes a_hi in-place (score) and a_lo
__global__ void softmax_kernel(float* __restrict__ score, float* __restrict__ a_lo,
                               const int* __restrict__ lens)
{
    int row = blockIdx.x;
    int b = row >> 10;
    int tid = threadIdx.x;
    float* r  = score + (size_t)row * TS;
    float* rl = a_lo  + (size_t)row * TS;
    int len = lens[b];

    float4 x = ((const float4*)r)[tid];
    float m = fmaxf(fmaxf(x.x, x.y), fmaxf(x.z, x.w));
    __shared__ float red[256];
    red[tid] = m;
    __syncthreads();
    for (int s = 128; s > 0; s >>= 1) {
        if (tid < s) red[tid] = fmaxf(red[tid], red[tid + s]);
        __syncthreads();
    }
    float rowmax = red[0];
    __syncthreads();

    int base = tid * 4;
    float e0 = (base + 0 < len) ? expf(x.x - rowmax) : 0.f;
    float e1 = (base + 1 < len) ? expf(x.y - rowmax) : 0.f;
    float e2 = (base + 2 < len) ? expf(x.z - rowmax) : 0.f;
    float e3 = (base + 3 < len) ? expf(x.w - rowmax) : 0.f;

    red[tid] = e0 + e1 + e2 + e3;
    __syncthreads();
    for (int s = 128; s > 0; s >>= 1) {
        if (tid < s) red[tid] += red[tid + s];
        __syncthreads();
    }
    float inv = 1.0f / red[0];

    float a0 = e0 * inv, a1 = e1 * inv, a2 = e2 * inv, a3 = e3 * inv;
    float4 hv, lv;
    hv.x = rna_tf32(a0); lv.x = rna_tf32(a0 - hv.x);
    hv.y = rna_tf32(a1); lv.y = rna_tf32(a1 - hv.y);
    hv.z = rna_tf32(a2); lv.z = rna_tf32(a2 - hv.z);
    hv.w = rna_tf32(a3); lv.w = rna_tf32(a3 - hv.w);
    ((float4*)r)[tid]  = hv;
    ((float4*)rl)[tid] = lv;
}

// ---------------------------------------------------------------------------
// Host launch
// ---------------------------------------------------------------------------
extern "C" void kernel_launch(void* const* d_in, const int* in_sizes, int n_in,
                              void* d_out, int out_size)
{
    const float* ht     = (const float*)d_in[0];
    const float* hs     = (const float*)d_in[1];
    const float* W_a    = (const float*)d_in[2];
    const float* W_c    = (const float*)d_in[3];
    const float* bias   = (const float*)d_in[4];
    const int*   source = (const int*)d_in[5];
    float* out = (float*)d_out;

    float *hs_hi, *hs_lo, *ht_hi, *ht_lo, *proj_hi, *proj_lo, *score, *a_lo;
    float *hsT_hi, *hsT_lo, *c_hi, *c_lo, *WaT_hi, *WaT_lo, *WcT_hi, *WcT_lo;
    int* lens;
    cudaGetSymbolAddress((void**)&hs_hi,   g_hs_hi);
    cudaGetSymbolAddress((void**)&hs_lo,   g_hs_lo);
    cudaGetSymbolAddress((void**)&ht_hi,   g_ht_hi);
    cudaGetSymbolAddress((void**)&ht_lo,   g_ht_lo);
    cudaGetSymbolAddress((void**)&proj_hi, g_proj_hi);
    cudaGetSymbolAddress((void**)&proj_lo, g_proj_lo);
    cudaGetSymbolAddress((void**)&score,   g_score);
    cudaGetSymbolAddress((void**)&a_lo,    g_a_lo);
    cudaGetSymbolAddress((void**)&hsT_hi,  g_hsT_hi);
    cudaGetSymbolAddress((void**)&hsT_lo,  g_hsT_lo);
    cudaGetSymbolAddress((void**)&c_hi,    g_c_hi);
    cudaGetSymbolAddress((void**)&c_lo,    g_c_lo);
    cudaGetSymbolAddress((void**)&WaT_hi,  g_WaT_hi);
    cudaGetSymbolAddress((void**)&WaT_lo,  g_WaT_lo);
    cudaGetSymbolAddress((void**)&WcT_hi,  g_WcT_hi);
    cudaGetSymbolAddress((void**)&WcT_lo,  g_WcT_lo);
    cudaGetSymbolAddress((void**)&lens,    g_lens);

    cudaFuncSetAttribute(gemm_mma<3,3>, cudaFuncAttributeMaxDynamicSharedMemorySize, GEMM_SMEM);
    cudaFuncSetAttribute(gemm_mma<0,3>, cudaFuncAttributeMaxDynamicSharedMemorySize, GEMM_SMEM);
    cudaFuncSetAttribute(gemm_mma<2,6>, cudaFuncAttributeMaxDynamicSharedMemorySize, GEMM_SMEM);

    // Preprocess: exact hi/lo splits
    lens_kernel<<<NB, 256>>>(source, lens);
    split_pair<<<2048, 256>>>(hs, hs_hi, hs_lo, (size_t)NB * TS * HH / 4);
    split_pair<<<2048, 256>>>(ht, ht_hi, ht_lo, (size_t)NB * TT * HH / 4);
    transpose_split<<<dim3(32, 32, 1),  dim3(32, 8)>>>(W_a, WaT_hi, WaT_lo, HH, HH);
    transpose_split<<<dim3(32, 64, 1),  dim3(32, 8)>>>(W_c, WcT_hi, WcT_lo, 2 * HH, OO);
    transpose_split<<<dim3(32, 32, NB), dim3(32, 8)>>>(hs, hsT_hi, hsT_lo, TS, HH);

    // G1: proj = hs @ W_a  (3xTF32), M=16384, EPI=split
    {
        SegArgs s{};
        s.a[0] = hs_hi;  s.a[1] = hs_lo;  s.a[2] = hs_hi;
        s.b[0] = WaT_hi; s.b[1] = WaT_hi; s.b[2] = WaT_lo;
        gemm_mma<3,3><<<dim3(HH/128, NB*TS/128, 1), 256, GEMM_SMEM>>>(
            s, proj_hi, proj_lo, nullptr, 1024, HH, 0, 0, 0);
    }

    // G2: score[b] = ht[b] @ proj[b]^T  (3xTF32), batched
    {
        SegArgs s{};
        s.a[0] = ht_hi;   s.a[1] = ht_lo;   s.a[2] = ht_hi;
        s.b[0] = proj_hi; s.b[1] = proj_hi; s.b[2] = proj_lo;
        gemm_mma<0,3><<<dim3(TS/128, TT/128, NB), 256, GEMM_SMEM>>>(
            s, score, nullptr, nullptr, 1024, TS,
            (long long)TT * HH, (long long)TS * HH, (long long)TT * TS);
    }

    // masked softmax -> a_hi (in score), a_lo
    softmax_kernel<<<NB * TT, 256>>>(score, a_lo, lens);

    // G3: c[b] = a[b] @ hs[b]  (3xTF32), batched, EPI=split
    {
        SegArgs s{};
        s.a[0] = score;  s.a[1] = a_lo;   s.a[2] = score;
        s.b[0] = hsT_hi; s.b[1] = hsT_hi; s.b[2] = hsT_lo;
        gemm_mma<3,3><<<dim3(HH/128, TT/128, NB), 256, GEMM_SMEM>>>(
            s, c_hi, c_lo, nullptr, 1024, HH,
            (long long)TT * TS, (long long)HH * TS, (long long)TT * HH);
    }

    // G4: out = tanh([c|ht] @ W_c + b)  (3xTF32 over K=2048 -> 6 segments)
    {
        SegArgs s{};
        s.a[0] = c_hi;  s.a[1] = ht_hi;  s.a[2] = c_lo;
        s.a[3] = ht_lo; s.a[4] = c_hi;   s.a[5] = ht_hi;
        s.b[0] = WcT_hi;        s.b[1] = WcT_hi + 1024;
        s.b[2] = WcT_hi;        s.b[3] = WcT_hi + 1024;
        s.b[4] = WcT_lo;        s.b[5] = WcT_lo + 1024;
        gemm_mma<2,6><<<dim3(OO/128, NB*TT/128, 1), 256, GEMM_SMEM>>>(
            s, out, nullptr, bias, 2048, OO, 0, 0, 0);
    }
}

// round 5
// speedup vs baseline: 2.4547x; 1.5963x over previous
#include <cuda_runtime.h>
#include <math.h>
#include <cstdint>

// Problem shape (fixed)
#define NB 16
#define TT 1024
#define TS 1024
#define HH 1024
#define OO 1024

// ---------------------------------------------------------------------------
// Scratch (device globals; no allocation). hi/lo = exact tf32 split pairs.
// ---------------------------------------------------------------------------
__device__ float g_hs_hi  [(size_t)NB * TS * HH];
__device__ float g_hs_lo  [(size_t)NB * TS * HH];
__device__ float g_ht_hi  [(size_t)NB * TT * HH];
__device__ float g_ht_lo  [(size_t)NB * TT * HH];
__device__ float g_proj_hi[(size_t)NB * TS * HH];
__device__ float g_proj_lo[(size_t)NB * TS * HH];
__device__ float g_score  [(size_t)NB * TT * TS];   // scores, then a (tf32) in-place
__device__ float g_hsT_hi [(size_t)NB * HH * TS];
__device__ float g_hsT_lo [(size_t)NB * HH * TS];
__device__ float g_c      [(size_t)NB * TT * HH];   // c rounded to tf32
__device__ float g_WaT_hi [(size_t)HH * HH];
__device__ float g_WaT_lo [(size_t)HH * HH];
__device__ float g_WcT_hi [(size_t)OO * 2 * HH];    // [O=1024][K=2048]
__device__ float g_WcT_lo [(size_t)OO * 2 * HH];
__device__ int   g_lens   [NB];

// ---------------------------------------------------------------------------
// Helpers / PTX (base ISA only — works through compute_103)
// ---------------------------------------------------------------------------
__device__ __forceinline__ uint32_t smem_u32(const void* p) {
    uint32_t a;
    asm("{ .reg .u64 t; cvta.to.shared.u64 t, %1; cvt.u32.u64 %0, t; }"
        : "=r"(a) : "l"(p));
    return a;
}
__device__ __forceinline__ float rna_tf32(float x) {
    uint32_t r; asm("cvt.rna.tf32.f32 %0, %1;" : "=r"(r) : "f"(x));
    return __uint_as_float(r);
}

#define CPASYNC16(saddr, gaddr) \
    asm volatile("cp.async.cg.shared.global [%0], [%1], 16;" :: "r"(saddr), "l"(gaddr))

__device__ __forceinline__ void ldm4(uint32_t* r, uint32_t addr) {
    asm volatile("ldmatrix.sync.aligned.m8n8.x4.shared.b16 {%0,%1,%2,%3}, [%4];"
                 : "=r"(r[0]), "=r"(r[1]), "=r"(r[2]), "=r"(r[3]) : "r"(addr));
}
__device__ __forceinline__ void mma8(float* c, const uint32_t* a, const uint32_t* b) {
    asm volatile(
        "mma.sync.aligned.m16n8k8.row.col.f32.tf32.tf32.f32 "
        "{%0,%1,%2,%3}, {%4,%5,%6,%7}, {%8,%9}, {%0,%1,%2,%3};"
        : "+f"(c[0]), "+f"(c[1]), "+f"(c[2]), "+f"(c[3])
        : "r"(a[0]), "r"(a[1]), "r"(a[2]), "r"(a[3]), "r"(b[0]), "r"(b[1]));
}

// Per-segment operand pointers (K = NSEG * 1024, segment k-width 1024)
struct SegArgs {
    const float* a[6];
    const float* b[6];
};

// ---------------------------------------------------------------------------
// tf32 mma.sync GEMM: C[M,N] = sum_seg A_seg[M,1024] * B_seg[N,1024]^T
// CTA tile 128x128, kstep 32, 256 thr = 8 warps (2x4), warp tile 64x32.
// 4-stage cp.async pipeline, SW128 xor swizzle, ldmatrix fragments.
// lda fixed 1024 for all A segments. ldb uniform per call.
// EPI: 0 plain, 1 round-to-tf32, 2 tanh(x+bias), 3 split -> C(hi), C2(lo).
// ---------------------------------------------------------------------------
static const int NSTG = 4;
static const int STAGE = 32768;                  // 16KB A + 16KB B
static const int GEMM_SMEM = 1024 + NSTG * STAGE;

template <int EPI, int NSEG>
__global__ __launch_bounds__(256, 1)
void gemm_mma(const SegArgs segs, float* __restrict__ C, float* __restrict__ C2,
              const float* __restrict__ bias, int ldb, int ldc,
              long long sA, long long sB, long long sC)
{
    extern __shared__ char smem[];
    const uint32_t data = (smem_u32(smem) + 1023) & ~1023u;

    const int tid  = threadIdx.x;
    const int lane = tid & 31;
    const int warp = tid >> 5;
    const int wm = (warp >> 2) << 6;     // 0 or 64
    const int wn = (warp & 3) << 5;      // 0,32,64,96
    const int bm = blockIdx.y << 7;
    const int bn = blockIdx.x << 7;

    const long long zA = (long long)blockIdx.z * sA;
    const long long zB = (long long)blockIdx.z * sB;
    float* Cb  = C + (size_t)blockIdx.z * sC;
    float* C2b = (EPI == 3) ? C2 + (size_t)blockIdx.z * sC : (float*)0;

    const int KT = NSEG * 32;            // k-steps of 32

    auto fill = [&](int kt, int s) {
        const int seg = kt >> 5;
        const int ka  = (kt & 31) << 5;
        const float* Ap = segs.a[seg] + zA;
        const float* Bp = segs.b[seg] + zB;
        const uint32_t sa = data + s * STAGE;
        const uint32_t sb = sa + 16384;
#pragma unroll
        for (int i = 0; i < 4; i++) {
            int c = tid + (i << 8);
            int row = c >> 3, ch = c & 7;
            const float* g = Ap + (size_t)(bm + row) * 1024 + ka + (ch << 2);
            CPASYNC16(sa + (row << 7) + (((ch ^ (row & 7))) << 4), g);
        }
#pragma unroll
        for (int i = 0; i < 4; i++) {
            int c = tid + (i << 8);
            int row = c >> 3, ch = c & 7;
            const float* g = Bp + (size_t)(bn + row) * ldb + ka + (ch << 2);
            CPASYNC16(sb + (row << 7) + (((ch ^ (row & 7))) << 4), g);
        }
    };

#pragma unroll
    for (int s = 0; s < NSTG - 1; s++) {
        fill(s, s);
        asm volatile("cp.async.commit_group;" ::: "memory");
    }

    float acc[4][4][4];
#pragma unroll
    for (int a = 0; a < 4; a++)
#pragma unroll
        for (int b = 0; b < 4; b++)
#pragma unroll
            for (int c = 0; c < 4; c++) acc[a][b][c] = 0.f;

    const int r8 = lane & 7;
    const int mh = lane >> 3;

    for (int kt = 0; kt < KT; kt++) {
        asm volatile("cp.async.wait_group 2;" ::: "memory");
        __syncthreads();

        int nf = kt + NSTG - 1;
        if (nf < KT) fill(nf, nf & (NSTG - 1));
        asm volatile("cp.async.commit_group;" ::: "memory");

        const uint32_t Ab = data + (kt & (NSTG - 1)) * STAGE;
        const uint32_t Bs = Ab + 16384;
#pragma unroll
        for (int k8 = 0; k8 < 4; k8++) {
            uint32_t af[4][4], bf[2][4];
#pragma unroll
            for (int mt = 0; mt < 4; mt++) {
                int arow = wm + mt * 16 + r8 + ((mh & 1) << 3);
                int achk = 2 * k8 + (mh >> 1);
                ldm4(af[mt], Ab + (arow << 7) + (((achk ^ (arow & 7))) << 4));
            }
#pragma unroll
            for (int p = 0; p < 2; p++) {
                int brow = wn + (p << 4) + r8 + ((mh >> 1) << 3);
                int bchk = 2 * k8 + (mh & 1);
                ldm4(bf[p], Bs + (brow << 7) + (((bchk ^ (brow & 7))) << 4));
            }
#pragma unroll
            for (int mt = 0; mt < 4; mt++)
#pragma unroll
                for (int nt = 0; nt < 4; nt++)
                    mma8(acc[mt][nt], af[mt], &bf[nt >> 1][(nt & 1) << 1]);
        }
    }

    const int row0 = bm + wm + (lane >> 2);
    const int col0 = bn + wn + ((lane & 3) << 1);
#pragma unroll
    for (int mt = 0; mt < 4; mt++) {
#pragma unroll
        for (int nt = 0; nt < 4; nt++) {
            int col = col0 + nt * 8;
#pragma unroll
            for (int h = 0; h < 2; h++) {
                int row = row0 + mt * 16 + h * 8;
                float v0 = acc[mt][nt][2 * h + 0];
                float v1 = acc[mt][nt][2 * h + 1];
                float* dst = Cb + (size_t)row * ldc + col;
                if (EPI == 0) {
                    float2 o = {v0, v1};
                    *(float2*)dst = o;
                } else if (EPI == 1) {
                    float2 o = {rna_tf32(v0), rna_tf32(v1)};
                    *(float2*)dst = o;
                } else if (EPI == 2) {
                    float2 o = {tanhf(v0 + bias[col]), tanhf(v1 + bias[col + 1])};
                    *(float2*)dst = o;
                } else {  // split
                    float h0 = rna_tf32(v0), h1 = rna_tf32(v1);
                    float2 oh = {h0, h1};
                    float2 ol = {rna_tf32(v0 - h0), rna_tf32(v1 - h1)};
                    *(float2*)dst = oh;
                    *(float2*)(C2b + (size_t)row * ldc + col) = ol;
                }
            }
        }
    }
}

// ---------------------------------------------------------------------------
// Preprocessing kernels
// ---------------------------------------------------------------------------
__global__ void split_pair(const float* __restrict__ in, float* __restrict__ hi,
                           float* __restrict__ lo, size_t n4)
{
    size_t i  = (size_t)blockIdx.x * blockDim.x + threadIdx.x;
    size_t st = (size_t)gridDim.x * blockDim.x;
    for (; i < n4; i += st) {
        float4 v = ((const float4*)in)[i];
        float4 h, l;
        h.x = rna_tf32(v.x); l.x = rna_tf32(v.x - h.x);
        h.y = rna_tf32(v.y); l.y = rna_tf32(v.y - h.y);
        h.z = rna_tf32(v.z); l.z = rna_tf32(v.z - h.z);
        h.w = rna_tf32(v.w); l.w = rna_tf32(v.w - h.w);
        ((float4*)hi)[i] = h;
        ((float4*)lo)[i] = l;
    }
}

// dst_{hi,lo}[c][r] = split(src[r][c]), batched over z
__global__ void transpose_split(const float* __restrict__ src, float* __restrict__ hi,
                                float* __restrict__ lo, int R, int C)
{
    __shared__ float t[32][33];
    size_t boff = (size_t)blockIdx.z * R * C;
    src += boff; hi += boff; lo += boff;
    int r0 = blockIdx.y << 5, c0 = blockIdx.x << 5;
    int tx = threadIdx.x, ty = threadIdx.y;
#pragma unroll
    for (int i = 0; i < 32; i += 8)
        t[ty + i][tx] = src[(size_t)(r0 + ty + i) * C + c0 + tx];
    __syncthreads();
#pragma unroll
    for (int i = 0; i < 32; i += 8) {
        float v = t[tx][ty + i];
        float h = rna_tf32(v), l = rna_tf32(v - h);
        size_t idx = (size_t)(c0 + ty + i) * R + r0 + tx;
        hi[idx] = h;
        lo[idx] = l;
    }
}

__global__ void lens_kernel(const int* __restrict__ source, int* __restrict__ lens)
{
    int b = blockIdx.x, tid = threadIdx.x;
    int cnt = 0;
    for (int s = tid; s < TS; s += blockDim.x)
        cnt += (source[(size_t)b * TS + s] != 0);
    __shared__ int red[256];
    red[tid] = cnt;
    __syncthreads();
    for (int s = 128; s > 0; s >>= 1) {
        if (tid < s) red[tid] += red[tid + s];
        __syncthreads();
    }
    if (tid == 0) lens[b] = red[0];
}

// masked softmax; writes a rounded to tf32, in-place
__global__ void softmax_kernel(float* __restrict__ score, const int* __restrict__ lens)
{
    int row = blockIdx.x;
    int b = row >> 10;
    int tid = threadIdx.x;
    float* r = score + (size_t)row * TS;
    int len = lens[b];

    float4 x = ((const float4*)r)[tid];
    float m = fmaxf(fmaxf(x.x, x.y), fmaxf(x.z, x.w));
    __shared__ float red[256];
    red[tid] = m;
    __syncthreads();
    for (int s = 128; s > 0; s >>= 1) {
        if (tid < s) red[tid] = fmaxf(red[tid], red[tid + s]);
        __syncthreads();
    }
    float rowmax = red[0];
    __syncthreads();

    int base = tid * 4;
    float e0 = (base + 0 < len) ? expf(x.x - rowmax) : 0.f;
    float e1 = (base + 1 < len) ? expf(x.y - rowmax) : 0.f;
    float e2 = (base + 2 < len) ? expf(x.z - rowmax) : 0.f;
    float e3 = (base + 3 < len) ? expf(x.w - rowmax) : 0.f;

    red[tid] = e0 + e1 + e2 + e3;
    __syncthreads();
    for (int s = 128; s > 0; s >>= 1) {
        if (tid < s) red[tid] += red[tid + s];
        __syncthreads();
    }
    float inv = 1.0f / red[0];

    float4 o = {rna_tf32(e0 * inv), rna_tf32(e1 * inv),
                rna_tf32(e2 * inv), rna_tf32(e3 * inv)};
    ((float4*)r)[tid] = o;
}

// ---------------------------------------------------------------------------
// Host launch
// ---------------------------------------------------------------------------
extern "C" void kernel_launch(void* const* d_in, const int* in_sizes, int n_in,
                              void* d_out, int out_size)
{
    const float* ht     = (const float*)d_in[0];
    const float* hs     = (const float*)d_in[1];
    const float* W_a    = (const float*)d_in[2];
    const float* W_c    = (const float*)d_in[3];
    const float* bias   = (const float*)d_in[4];
    const int*   source = (const int*)d_in[5];
    float* out = (float*)d_out;

    float *hs_hi, *hs_lo, *ht_hi, *ht_lo, *proj_hi, *proj_lo, *score;
    float *hsT_hi, *hsT_lo, *c, *WaT_hi, *WaT_lo, *WcT_hi, *WcT_lo;
    int* lens;
    cudaGetSymbolAddress((void**)&hs_hi,   g_hs_hi);
    cudaGetSymbolAddress((void**)&hs_lo,   g_hs_lo);
    cudaGetSymbolAddress((void**)&ht_hi,   g_ht_hi);
    cudaGetSymbolAddress((void**)&ht_lo,   g_ht_lo);
    cudaGetSymbolAddress((void**)&proj_hi, g_proj_hi);
    cudaGetSymbolAddress((void**)&proj_lo, g_proj_lo);
    cudaGetSymbolAddress((void**)&score,   g_score);
    cudaGetSymbolAddress((void**)&hsT_hi,  g_hsT_hi);
    cudaGetSymbolAddress((void**)&hsT_lo,  g_hsT_lo);
    cudaGetSymbolAddress((void**)&c,       g_c);
    cudaGetSymbolAddress((void**)&WaT_hi,  g_WaT_hi);
    cudaGetSymbolAddress((void**)&WaT_lo,  g_WaT_lo);
    cudaGetSymbolAddress((void**)&WcT_hi,  g_WcT_hi);
    cudaGetSymbolAddress((void**)&WcT_lo,  g_WcT_lo);
    cudaGetSymbolAddress((void**)&lens,    g_lens);

    cudaFuncSetAttribute(gemm_mma<3,3>, cudaFuncAttributeMaxDynamicSharedMemorySize, GEMM_SMEM);
    cudaFuncSetAttribute(gemm_mma<0,3>, cudaFuncAttributeMaxDynamicSharedMemorySize, GEMM_SMEM);
    cudaFuncSetAttribute(gemm_mma<1,1>, cudaFuncAttributeMaxDynamicSharedMemorySize, GEMM_SMEM);
    cudaFuncSetAttribute(gemm_mma<2,2>, cudaFuncAttributeMaxDynamicSharedMemorySize, GEMM_SMEM);

    // Preprocess: exact hi/lo splits
    lens_kernel<<<NB, 256>>>(source, lens);
    split_pair<<<2048, 256>>>(hs, hs_hi, hs_lo, (size_t)NB * TS * HH / 4);
    split_pair<<<2048, 256>>>(ht, ht_hi, ht_lo, (size_t)NB * TT * HH / 4);
    transpose_split<<<dim3(32, 32, 1),  dim3(32, 8)>>>(W_a, WaT_hi, WaT_lo, HH, HH);
    transpose_split<<<dim3(32, 64, 1),  dim3(32, 8)>>>(W_c, WcT_hi, WcT_lo, 2 * HH, OO);
    transpose_split<<<dim3(32, 32, NB), dim3(32, 8)>>>(hs, hsT_hi, hsT_lo, TS, HH);

    // G1: proj = hs @ W_a  (3xTF32), M=16384, EPI=split -> proj_hi, proj_lo
    {
        SegArgs s{};
        s.a[0] = hs_hi;  s.a[1] = hs_lo;  s.a[2] = hs_hi;
        s.b[0] = WaT_hi; s.b[1] = WaT_hi; s.b[2] = WaT_lo;
        gemm_mma<3,3><<<dim3(HH/128, NB*TS/128, 1), 256, GEMM_SMEM>>>(
            s, proj_hi, proj_lo, nullptr, 1024, HH, 0, 0, 0);
    }

    // G2: score[b] = ht[b] @ proj[b]^T  (3xTF32), batched, EPI=plain
    {
        SegArgs s{};
        s.a[0] = ht_hi;   s.a[1] = ht_lo;   s.a[2] = ht_hi;
        s.b[0] = proj_hi; s.b[1] = proj_hi; s.b[2] = proj_lo;
        gemm_mma<0,3><<<dim3(TS/128, TT/128, NB), 256, GEMM_SMEM>>>(
            s, score, nullptr, nullptr, 1024, TS,
            (long long)TT * HH, (long long)TS * HH, (long long)TT * TS);
    }

    // masked softmax -> a (tf32-rounded, in score)
    softmax_kernel<<<NB * TT, 256>>>(score, lens);

    // G3: c[b] = a[b] @ hs[b]  (single tf32), batched, EPI=round -> c
    {
        SegArgs s{};
        s.a[0] = score;
        s.b[0] = hsT_hi;
        gemm_mma<1,1><<<dim3(HH/128, TT/128, NB), 256, GEMM_SMEM>>>(
            s, c, nullptr, nullptr, 1024, HH,
            (long long)TT * TS, (long long)HH * TS, (long long)TT * HH);
    }

    // G4: out = tanh([c|ht] @ W_c + b)  (single tf32, 2 segments over K=2048)
    {
        SegArgs s{};
        s.a[0] = c;      s.a[1] = ht_hi;
        s.b[0] = WcT_hi; s.b[1] = WcT_hi + 1024;
        gemm_mma<2,2><<<dim3(OO/128, NB*TT/128, 1), 256, GEMM_SMEM>>>(
            s, out, nullptr, bias, 2048, OO, 0, 0, 0);
    }
}

// round 6
// speedup vs baseline: 3.4953x; 1.4239x over previous
#include <cuda_runtime.h>
#include <cuda_bf16.h>
#include <math.h>
#include <cstdint>

// Problem shape (fixed)
#define NB 16
#define TT 1024
#define TS 1024
#define HH 1024
#define OO 1024

// ---------------------------------------------------------------------------
// Scratch (device globals; no allocation)
// ---------------------------------------------------------------------------
__device__ __nv_bfloat16 g_hs_bh  [(size_t)NB * TS * HH];
__device__ __nv_bfloat16 g_hs_bl  [(size_t)NB * TS * HH];
__device__ __nv_bfloat16 g_ht_bh  [(size_t)NB * TT * HH];
__device__ __nv_bfloat16 g_ht_bl  [(size_t)NB * TT * HH];
__device__ __nv_bfloat16 g_WaT_bh [(size_t)HH * HH];
__device__ __nv_bfloat16 g_WaT_bl [(size_t)HH * HH];
__device__ __nv_bfloat16 g_proj_bh[(size_t)NB * TS * HH];
__device__ __nv_bfloat16 g_proj_bl[(size_t)NB * TS * HH];
__device__ float g_score [(size_t)NB * TT * TS];   // scores, then a (tf32) in-place
__device__ float g_hsT_hi[(size_t)NB * HH * TS];   // hs^T tf32-rounded
__device__ float g_c     [(size_t)NB * TT * HH];   // c tf32-rounded
__device__ float g_ht_hi [(size_t)NB * TT * HH];   // ht tf32-rounded (G4)
__device__ float g_WcT_hi[(size_t)OO * 2 * HH];    // [O=1024][K=2048] tf32
__device__ int   g_lens  [NB];

// ---------------------------------------------------------------------------
// Helpers / PTX (base ISA only)
// ---------------------------------------------------------------------------
__device__ __forceinline__ uint32_t smem_u32(const void* p) {
    uint32_t a;
    asm("{ .reg .u64 t; cvta.to.shared.u64 t, %1; cvt.u32.u64 %0, t; }"
        : "=r"(a) : "l"(p));
    return a;
}
__device__ __forceinline__ float rna_tf32(float x) {
    uint32_t r; asm("cvt.rna.tf32.f32 %0, %1;" : "=r"(r) : "f"(x));
    return __uint_as_float(r);
}

#define CPASYNC16(saddr, gaddr) \
    asm volatile("cp.async.cg.shared.global [%0], [%1], 16;" :: "r"(saddr), "l"(gaddr))

__device__ __forceinline__ void ldm4(uint32_t* r, uint32_t addr) {
    asm volatile("ldmatrix.sync.aligned.m8n8.x4.shared.b16 {%0,%1,%2,%3}, [%4];"
                 : "=r"(r[0]), "=r"(r[1]), "=r"(r[2]), "=r"(r[3]) : "r"(addr));
}
__device__ __forceinline__ void mma8(float* c, const uint32_t* a, const uint32_t* b) {
    asm volatile(
        "mma.sync.aligned.m16n8k8.row.col.f32.tf32.tf32.f32 "
        "{%0,%1,%2,%3}, {%4,%5,%6,%7}, {%8,%9}, {%0,%1,%2,%3};"
        : "+f"(c[0]), "+f"(c[1]), "+f"(c[2]), "+f"(c[3])
        : "r"(a[0]), "r"(a[1]), "r"(a[2]), "r"(a[3]), "r"(b[0]), "r"(b[1]));
}
__device__ __forceinline__ void mma16(float* c, const uint32_t* a, const uint32_t* b) {
    asm volatile(
        "mma.sync.aligned.m16n8k16.row.col.f32.bf16.bf16.f32 "
        "{%0,%1,%2,%3}, {%4,%5,%6,%7}, {%8,%9}, {%0,%1,%2,%3};"
        : "+f"(c[0]), "+f"(c[1]), "+f"(c[2]), "+f"(c[3])
        : "r"(a[0]), "r"(a[1]), "r"(a[2]), "r"(a[3]), "r"(b[0]), "r"(b[1]));
}

struct SegArgs  { const float* a[3];          const float* b[3];          };
struct SegArgsB { const __nv_bfloat16* a[3];  const __nv_bfloat16* b[3];  };

static const int NSTG = 4;
static const int STAGE = 32768;                  // 16KB A + 16KB B
static const int GEMM_SMEM = 1024 + NSTG * STAGE;

// ---------------------------------------------------------------------------
// tf32 GEMM (as R5): C[M,N] = sum_seg A_seg[M,1024] * B_seg[N,1024]^T
// EPI: 1 round-to-tf32, 2 tanh(x+bias)
// ---------------------------------------------------------------------------
template <int EPI, int NSEG>
__global__ __launch_bounds__(256, 1)
void gemm_mma(const SegArgs segs, float* __restrict__ C,
              const float* __restrict__ bias, int ldb, int ldc,
              long long sA, long long sB, long long sC)
{
    extern __shared__ char smem[];
    const uint32_t data = (smem_u32(smem) + 1023) & ~1023u;

    const int tid  = threadIdx.x;
    const int lane = tid & 31;
    const int warp = tid >> 5;
    const int wm = (warp >> 2) << 6;
    const int wn = (warp & 3) << 5;
    const int bm = blockIdx.y << 7;
    const int bn = blockIdx.x << 7;

    const long long zA = (long long)blockIdx.z * sA;
    const long long zB = (long long)blockIdx.z * sB;
    float* Cb = C + (size_t)blockIdx.z * sC;

    const int KT = NSEG * 32;

    auto fill = [&](int kt, int s) {
        const int seg = kt >> 5;
        const int ka  = (kt & 31) << 5;
        const float* Ap = segs.a[seg] + zA;
        const float* Bp = segs.b[seg] + zB;
        const uint32_t sa = data + s * STAGE;
        const uint32_t sb = sa + 16384;
#pragma unroll
        for (int i = 0; i < 4; i++) {
            int c = tid + (i << 8);
            int row = c >> 3, ch = c & 7;
            const float* g = Ap + (size_t)(bm + row) * 1024 + ka + (ch << 2);
            CPASYNC16(sa + (row << 7) + (((ch ^ (row & 7))) << 4), g);
        }
#pragma unroll
        for (int i = 0; i < 4; i++) {
            int c = tid + (i << 8);
            int row = c >> 3, ch = c & 7;
            const float* g = Bp + (size_t)(bn + row) * ldb + ka + (ch << 2);
            CPASYNC16(sb + (row << 7) + (((ch ^ (row & 7))) << 4), g);
        }
    };

#pragma unroll
    for (int s = 0; s < NSTG - 1; s++) {
        fill(s, s);
        asm volatile("cp.async.commit_group;" ::: "memory");
    }

    float acc[4][4][4];
#pragma unroll
    for (int a = 0; a < 4; a++)
#pragma unroll
        for (int b = 0; b < 4; b++)
#pragma unroll
            for (int c = 0; c < 4; c++) acc[a][b][c] = 0.f;

    const int r8 = lane & 7;
    const int mh = lane >> 3;

    for (int kt = 0; kt < KT; kt++) {
        asm volatile("cp.async.wait_group 2;" ::: "memory");
        __syncthreads();

        int nf = kt + NSTG - 1;
        if (nf < KT) fill(nf, nf & (NSTG - 1));
        asm volatile("cp.async.commit_group;" ::: "memory");

        const uint32_t Ab = data + (kt & (NSTG - 1)) * STAGE;
        const uint32_t Bs = Ab + 16384;
#pragma unroll
        for (int k8 = 0; k8 < 4; k8++) {
            uint32_t af[4][4], bf[2][4];
#pragma unroll
            for (int mt = 0; mt < 4; mt++) {
                int arow = wm + mt * 16 + r8 + ((mh & 1) << 3);
                int achk = 2 * k8 + (mh >> 1);
                ldm4(af[mt], Ab + (arow << 7) + (((achk ^ (arow & 7))) << 4));
            }
#pragma unroll
            for (int p = 0; p < 2; p++) {
                int brow = wn + (p << 4) + r8 + ((mh >> 1) << 3);
                int bchk = 2 * k8 + (mh & 1);
                ldm4(bf[p], Bs + (brow << 7) + (((bchk ^ (brow & 7))) << 4));
            }
#pragma unroll
            for (int mt = 0; mt < 4; mt++)
#pragma unroll
                for (int nt = 0; nt < 4; nt++)
                    mma8(acc[mt][nt], af[mt], &bf[nt >> 1][(nt & 1) << 1]);
        }
    }

    const int row0 = bm + wm + (lane >> 2);
    const int col0 = bn + wn + ((lane & 3) << 1);
#pragma unroll
    for (int mt = 0; mt < 4; mt++) {
#pragma unroll
        for (int nt = 0; nt < 4; nt++) {
            int col = col0 + nt * 8;
#pragma unroll
            for (int h = 0; h < 2; h++) {
                int row = row0 + mt * 16 + h * 8;
                float v0 = acc[mt][nt][2 * h + 0];
                float v1 = acc[mt][nt][2 * h + 1];
                float* dst = Cb + (size_t)row * ldc + col;
                if (EPI == 1) {
                    float2 o = {rna_tf32(v0), rna_tf32(v1)};
                    *(float2*)dst = o;
                } else {  // EPI == 2
                    float2 o = {tanhf(v0 + bias[col]), tanhf(v1 + bias[col + 1])};
                    *(float2*)dst = o;
                }
            }
        }
    }
}

// ---------------------------------------------------------------------------
// bf16 GEMM: C[M,N] = sum_seg A_seg[M,1024] * B_seg[N,1024]^T  (bf16 in, fp32 acc)
// k-step per stage = 64 elements (128B rows). EPI: 0 fp32 out, 4 split->bh,bl
// ---------------------------------------------------------------------------
template <int EPI, int NSEG>
__global__ __launch_bounds__(256, 1)
void gemm_bf16(const SegArgsB segs, float* __restrict__ Cf,
               __nv_bfloat16* __restrict__ Chi, __nv_bfloat16* __restrict__ Clo,
               int ldb, int ldc, long long sA, long long sB, long long sC)
{
    extern __shared__ char smem[];
    const uint32_t data = (smem_u32(smem) + 1023) & ~1023u;

    const int tid  = threadIdx.x;
    const int lane = tid & 31;
    const int warp = tid >> 5;
    const int wm = (warp >> 2) << 6;
    const int wn = (warp & 3) << 5;
    const int bm = blockIdx.y << 7;
    const int bn = blockIdx.x << 7;

    const long long zA = (long long)blockIdx.z * sA;
    const long long zB = (long long)blockIdx.z * sB;

    const int KT = NSEG * 16;            // k-steps of 64 bf16

    auto fill = [&](int kt, int s) {
        const int seg = kt >> 4;
        const int ka  = (kt & 15) << 6;
        const __nv_bfloat16* Ap = segs.a[seg] + zA;
        const __nv_bfloat16* Bp = segs.b[seg] + zB;
        const uint32_t sa = data + s * STAGE;
        const uint32_t sb = sa + 16384;
#pragma unroll
        for (int i = 0; i < 4; i++) {
            int c = tid + (i << 8);
            int row = c >> 3, ch = c & 7;
            const __nv_bfloat16* g = Ap + (size_t)(bm + row) * 1024 + ka + (ch << 3);
            CPASYNC16(sa + (row << 7) + (((ch ^ (row & 7))) << 4), g);
        }
#pragma unroll
        for (int i = 0; i < 4; i++) {
            int c = tid + (i << 8);
            int row = c >> 3, ch = c & 7;
            const __nv_bfloat16* g = Bp + (size_t)(bn + row) * ldb + ka + (ch << 3);
            CPASYNC16(sb + (row << 7) + (((ch ^ (row & 7))) << 4), g);
        }
    };

#pragma unroll
    for (int s = 0; s < NSTG - 1; s++) {
        fill(s, s);
        asm volatile("cp.async.commit_group;" ::: "memory");
    }

    float acc[4][4][4];
#pragma unroll
    for (int a = 0; a < 4; a++)
#pragma unroll
        for (int b = 0; b < 4; b++)
#pragma unroll
            for (int c = 0; c < 4; c++) acc[a][b][c] = 0.f;

    const int r8   = lane & 7;
    const int tile = lane >> 3;              // 0..3
    const int amo  = (tile & 1) << 3;        // A: +8 m for odd tiles
    const int akc  = tile >> 1;              // A: k-chunk select
    const int bno  = (lane >> 4) << 3;       // B: +8 n for lanes 16+
    const int bkc  = (lane >> 3) & 1;        // B: k-chunk select

    for (int kt = 0; kt < KT; kt++) {
        asm volatile("cp.async.wait_group 2;" ::: "memory");
        __syncthreads();

        int nf = kt + NSTG - 1;
        if (nf < KT) fill(nf, nf & (NSTG - 1));
        asm volatile("cp.async.commit_group;" ::: "memory");

        const uint32_t Ab = data + (kt & (NSTG - 1)) * STAGE;
        const uint32_t Bs = Ab + 16384;
#pragma unroll
        for (int k16 = 0; k16 < 4; k16++) {
            uint32_t af[4][4], bf[2][4];
#pragma unroll
            for (int mt = 0; mt < 4; mt++) {
                int arow = wm + mt * 16 + r8 + amo;
                int achk = 2 * k16 + akc;
                ldm4(af[mt], Ab + (arow << 7) + (((achk ^ (arow & 7))) << 4));
            }
#pragma unroll
            for (int p = 0; p < 2; p++) {
                int brow = wn + (p << 4) + r8 + bno;
                int bchk = 2 * k16 + bkc;
                ldm4(bf[p], Bs + (brow << 7) + (((bchk ^ (brow & 7))) << 4));
            }
#pragma unroll
            for (int mt = 0; mt < 4; mt++)
#pragma unroll
                for (int nt = 0; nt < 4; nt++)
                    mma16(acc[mt][nt], af[mt], &bf[nt >> 1][(nt & 1) << 1]);
        }
    }

    const int row0 = bm + wm + (lane >> 2);
    const int col0 = bn + wn + ((lane & 3) << 1);
#pragma unroll
    for (int mt = 0; mt < 4; mt++) {
#pragma unroll
        for (int nt = 0; nt < 4; nt++) {
            int col = col0 + nt * 8;
#pragma unroll
            for (int h = 0; h < 2; h++) {
                int row = row0 + mt * 16 + h * 8;
                float v0 = acc[mt][nt][2 * h + 0];
                float v1 = acc[mt][nt][2 * h + 1];
                if (EPI == 0) {
                    float* dst = Cf + (size_t)blockIdx.z * sC + (size_t)row * ldc + col;
                    float2 o = {v0, v1};
                    *(float2*)dst = o;
                } else {  // EPI == 4: split to bf16 pairs
                    __nv_bfloat16 h0 = __float2bfloat16_rn(v0);
                    __nv_bfloat16 h1 = __float2bfloat16_rn(v1);
                    __nv_bfloat162 hv; hv.x = h0; hv.y = h1;
                    __nv_bfloat162 lv;
                    lv.x = __float2bfloat16_rn(v0 - __bfloat162float(h0));
                    lv.y = __float2bfloat16_rn(v1 - __bfloat162float(h1));
                    size_t off = (size_t)blockIdx.z * sC + (size_t)row * ldc + col;
                    *(__nv_bfloat162*)(Chi + off) = hv;
                    *(__nv_bfloat162*)(Clo + off) = lv;
                }
            }
        }
    }
}

// ---------------------------------------------------------------------------
// Preprocessing kernels
// ---------------------------------------------------------------------------
__global__ void split_bf16(const float* __restrict__ in, __nv_bfloat16* __restrict__ hi,
                           __nv_bfloat16* __restrict__ lo, size_t n4)
{
    size_t i  = (size_t)blockIdx.x * blockDim.x + threadIdx.x;
    size_t st = (size_t)gridDim.x * blockDim.x;
    for (; i < n4; i += st) {
        float4 v = ((const float4*)in)[i];
        __nv_bfloat162 h0, h1, l0, l1;
        h0.x = __float2bfloat16_rn(v.x); l0.x = __float2bfloat16_rn(v.x - __bfloat162float(h0.x));
        h0.y = __float2bfloat16_rn(v.y); l0.y = __float2bfloat16_rn(v.y - __bfloat162float(h0.y));
        h1.x = __float2bfloat16_rn(v.z); l1.x = __float2bfloat16_rn(v.z - __bfloat162float(h1.x));
        h1.y = __float2bfloat16_rn(v.w); l1.y = __float2bfloat16_rn(v.w - __bfloat162float(h1.y));
        ((__nv_bfloat162*)hi)[2 * i]     = h0;
        ((__nv_bfloat162*)hi)[2 * i + 1] = h1;
        ((__nv_bfloat162*)lo)[2 * i]     = l0;
        ((__nv_bfloat162*)lo)[2 * i + 1] = l1;
    }
}

__global__ void round_copy(const float* __restrict__ in, float* __restrict__ out,
                           size_t n4)
{
    size_t i  = (size_t)blockIdx.x * blockDim.x + threadIdx.x;
    size_t st = (size_t)gridDim.x * blockDim.x;
    for (; i < n4; i += st) {
        float4 v = ((const float4*)in)[i];
        v.x = rna_tf32(v.x); v.y = rna_tf32(v.y);
        v.z = rna_tf32(v.z); v.w = rna_tf32(v.w);
        ((float4*)out)[i] = v;
    }
}

// dst[c][r] = round_tf32(src[r][c]), batched over z
__global__ void transpose_round(const float* __restrict__ src, float* __restrict__ dst,
                                int R, int C)
{
    __shared__ float t[32][33];
    size_t boff = (size_t)blockIdx.z * R * C;
    src += boff; dst += boff;
    int r0 = blockIdx.y << 5, c0 = blockIdx.x << 5;
    int tx = threadIdx.x, ty = threadIdx.y;
#pragma unroll
    for (int i = 0; i < 32; i += 8)
        t[ty + i][tx] = src[(size_t)(r0 + ty + i) * C + c0 + tx];
    __syncthreads();
#pragma unroll
    for (int i = 0; i < 32; i += 8)
        dst[(size_t)(c0 + ty + i) * R + r0 + tx] = rna_tf32(t[tx][ty + i]);
}

// dst_{bh,bl}[c][r] = bf16-split(src[r][c])
__global__ void transpose_split_bf16(const float* __restrict__ src,
                                     __nv_bfloat16* __restrict__ hi,
                                     __nv_bfloat16* __restrict__ lo, int R, int C)
{
    __shared__ float t[32][33];
    int r0 = blockIdx.y << 5, c0 = blockIdx.x << 5;
    int tx = threadIdx.x, ty = threadIdx.y;
#pragma unroll
    for (int i = 0; i < 32; i += 8)
        t[ty + i][tx] = src[(size_t)(r0 + ty + i) * C + c0 + tx];
    __syncthreads();
#pragma unroll
    for (int i = 0; i < 32; i += 8) {
        float v = t[tx][ty + i];
        __nv_bfloat16 h = __float2bfloat16_rn(v);
        __nv_bfloat16 l = __float2bfloat16_rn(v - __bfloat162float(h));
        size_t idx = (size_t)(c0 + ty + i) * R + r0 + tx;
        hi[idx] = h;
        lo[idx] = l;
    }
}

__global__ void lens_kernel(const int* __restrict__ source, int* __restrict__ lens)
{
    int b = blockIdx.x, tid = threadIdx.x;
    int cnt = 0;
    for (int s = tid; s < TS; s += blockDim.x)
        cnt += (source[(size_t)b * TS + s] != 0);
    __shared__ int red[256];
    red[tid] = cnt;
    __syncthreads();
    for (int s = 128; s > 0; s >>= 1) {
        if (tid < s) red[tid] += red[tid + s];
        __syncthreads();
    }
    if (tid == 0) lens[b] = red[0];
}

// masked softmax; writes a rounded to tf32, in-place
__global__ void softmax_kernel(float* __restrict__ score, const int* __restrict__ lens)
{
    int row = blockIdx.x;
    int b = row >> 10;
    int tid = threadIdx.x;
    float* r = score + (size_t)row * TS;
    int len = lens[b];

    float4 x = ((const float4*)r)[tid];
    float m = fmaxf(fmaxf(x.x, x.y), fmaxf(x.z, x.w));
    __shared__ float red[256];
    red[tid] = m;
    __syncthreads();
    for (int s = 128; s > 0; s >>= 1) {
        if (tid < s) red[tid] = fmaxf(red[tid], red[tid + s]);
        __syncthreads();
    }
    float rowmax = red[0];
    __syncthreads();

    int base = tid * 4;
    float e0 = (base + 0 < len) ? expf(x.x - rowmax) : 0.f;
    float e1 = (base + 1 < len) ? expf(x.y - rowmax) : 0.f;
    float e2 = (base + 2 < len) ? expf(x.z - rowmax) : 0.f;
    float e3 = (base + 3 < len) ? expf(x.w - rowmax) : 0.f;

    red[tid] = e0 + e1 + e2 + e3;
    __syncthreads();
    for (int s = 128; s > 0; s >>= 1) {
        if (tid < s) red[tid] += red[tid + s];
        __syncthreads();
    }
    float inv = 1.0f / red[0];

    float4 o = {rna_tf32(e0 * inv), rna_tf32(e1 * inv),
                rna_tf32(e2 * inv), rna_tf32(e3 * inv)};
    ((float4*)r)[tid] = o;
}

// ---------------------------------------------------------------------------
// Host launch
// ---------------------------------------------------------------------------
extern "C" void kernel_launch(void* const* d_in, const int* in_sizes, int n_in,
                              void* d_out, int out_size)
{
    const float* ht     = (const float*)d_in[0];
    const float* hs     = (const float*)d_in[1];
    const float* W_a    = (const float*)d_in[2];
    const float* W_c    = (const float*)d_in[3];
    const float* bias   = (const float*)d_in[4];
    const int*   source = (const int*)d_in[5];
    float* out = (float*)d_out;

    __nv_bfloat16 *hs_bh, *hs_bl, *ht_bh, *ht_bl, *WaT_bh, *WaT_bl, *proj_bh, *proj_bl;
    float *score, *hsT_hi, *c, *ht_hi, *WcT_hi;
    int* lens;
    cudaGetSymbolAddress((void**)&hs_bh,   g_hs_bh);
    cudaGetSymbolAddress((void**)&hs_bl,   g_hs_bl);
    cudaGetSymbolAddress((void**)&ht_bh,   g_ht_bh);
    cudaGetSymbolAddress((void**)&ht_bl,   g_ht_bl);
    cudaGetSymbolAddress((void**)&WaT_bh,  g_WaT_bh);
    cudaGetSymbolAddress((void**)&WaT_bl,  g_WaT_bl);
    cudaGetSymbolAddress((void**)&proj_bh, g_proj_bh);
    cudaGetSymbolAddress((void**)&proj_bl, g_proj_bl);
    cudaGetSymbolAddress((void**)&score,   g_score);
    cudaGetSymbolAddress((void**)&hsT_hi,  g_hsT_hi);
    cudaGetSymbolAddress((void**)&c,       g_c);
    cudaGetSymbolAddress((void**)&ht_hi,   g_ht_hi);
    cudaGetSymbolAddress((void**)&WcT_hi,  g_WcT_hi);
    cudaGetSymbolAddress((void**)&lens,    g_lens);

    cudaFuncSetAttribute(gemm_bf16<4,3>, cudaFuncAttributeMaxDynamicSharedMemorySize, GEMM_SMEM);
    cudaFuncSetAttribute(gemm_bf16<0,3>, cudaFuncAttributeMaxDynamicSharedMemorySize, GEMM_SMEM);
    cudaFuncSetAttribute(gemm_mma<1,1>,  cudaFuncAttributeMaxDynamicSharedMemorySize, GEMM_SMEM);
    cudaFuncSetAttribute(gemm_mma<2,2>,  cudaFuncAttributeMaxDynamicSharedMemorySize, GEMM_SMEM);

    // Preprocess
    lens_kernel<<<NB, 256>>>(source, lens);
    split_bf16<<<2048, 256>>>(hs, hs_bh, hs_bl, (size_t)NB * TS * HH / 4);
    split_bf16<<<2048, 256>>>(ht, ht_bh, ht_bl, (size_t)NB * TT * HH / 4);
    round_copy<<<2048, 256>>>(ht, ht_hi, (size_t)NB * TT * HH / 4);
    transpose_split_bf16<<<dim3(32, 32), dim3(32, 8)>>>(W_a, WaT_bh, WaT_bl, HH, HH);
    transpose_round<<<dim3(32, 32, NB), dim3(32, 8)>>>(hs, hsT_hi, TS, HH);
    transpose_round<<<dim3(32, 64, 1),  dim3(32, 8)>>>(W_c, WcT_hi, 2 * HH, OO);

    // G1: proj = hs @ W_a  (3xBF16), EPI=split -> proj_bh, proj_bl
    {
        SegArgsB s{};
        s.a[0] = hs_bh;  s.a[1] = hs_bl;  s.a[2] = hs_bh;
        s.b[0] = WaT_bh; s.b[1] = WaT_bh; s.b[2] = WaT_bl;
        gemm_bf16<4,3><<<dim3(HH/128, NB*TS/128, 1), 256, GEMM_SMEM>>>(
            s, nullptr, proj_bh, proj_bl, 1024, HH, 0, 0, (long long)0);
    }

    // G2: score[b] = ht[b] @ proj[b]^T  (3xBF16), batched, EPI=plain fp32
    {
        SegArgsB s{};
        s.a[0] = ht_bh;   s.a[1] = ht_bl;   s.a[2] = ht_bh;
        s.b[0] = proj_bh; s.b[1] = proj_bh; s.b[2] = proj_bl;
        gemm_bf16<0,3><<<dim3(TS/128, TT/128, NB), 256, GEMM_SMEM>>>(
            s, score, nullptr, nullptr, 1024, TS,
            (long long)TT * HH, (long long)TS * HH, (long long)TT * TS);
    }

    // masked softmax -> a (tf32-rounded, in score)
    softmax_kernel<<<NB * TT, 256>>>(score, lens);

    // G3: c[b] = a[b] @ hs[b]  (single tf32), EPI=round -> c
    {
        SegArgs s{};
        s.a[0] = score;
        s.b[0] = hsT_hi;
        gemm_mma<1,1><<<dim3(HH/128, TT/128, NB), 256, GEMM_SMEM>>>(
            s, c, nullptr, 1024, HH,
            (long long)TT * TS, (long long)HH * TS, (long long)TT * HH);
    }

    // G4: out = tanh([c|ht] @ W_c + b)  (single tf32, 2 segments over K=2048)
    {
        SegArgs s{};
        s.a[0] = c;      s.a[1] = ht_hi;
        s.b[0] = WcT_hi; s.b[1] = WcT_hi + 1024;
        gemm_mma<2,2><<<dim3(OO/128, NB*TT/128, 1), 256, GEMM_SMEM>>>(
            s, out, bias, 2048, OO, 0, 0, 0);
    }
}

// round 7
// speedup vs baseline: 4.2884x; 1.2269x over previous
#include <cuda_runtime.h>
#include <cuda_bf16.h>
#include <math.h>
#include <cstdint>

// Problem shape (fixed)
#define NB 16
#define TT 1024
#define TS 1024
#define HH 1024
#define OO 1024

// ---------------------------------------------------------------------------
// Scratch (device globals; no allocation)
// ---------------------------------------------------------------------------
__device__ __nv_bfloat16 g_hs_bh  [(size_t)NB * TS * HH];
__device__ __nv_bfloat16 g_hs_bl  [(size_t)NB * TS * HH];
__device__ __nv_bfloat16 g_ht_bh  [(size_t)NB * TT * HH];
__device__ __nv_bfloat16 g_ht_bl  [(size_t)NB * TT * HH];
__device__ __nv_bfloat16 g_WaT_bh [(size_t)HH * HH];
__device__ __nv_bfloat16 g_WaT_bl [(size_t)HH * HH];
__device__ __nv_bfloat16 g_proj_bh[(size_t)NB * TS * HH];
__device__ __nv_bfloat16 g_proj_bl[(size_t)NB * TS * HH];
__device__ float g_score [(size_t)NB * TT * TS];   // scores, then a (tf32) in-place
__device__ float g_hsT_hi[(size_t)NB * HH * TS];   // hs^T tf32-rounded
__device__ float g_c     [(size_t)NB * TT * HH];   // c tf32-rounded
__device__ float g_ht_hi [(size_t)NB * TT * HH];   // ht tf32-rounded (G4)
__device__ float g_WcT_hi[(size_t)OO * 2 * HH];    // [O=1024][K=2048] tf32
__device__ int   g_lens  [NB];

// ---------------------------------------------------------------------------
// Helpers / PTX (base ISA only)
// ---------------------------------------------------------------------------
__device__ __forceinline__ uint32_t smem_u32(const void* p) {
    uint32_t a;
    asm("{ .reg .u64 t; cvta.to.shared.u64 t, %1; cvt.u32.u64 %0, t; }"
        : "=r"(a) : "l"(p));
    return a;
}
__device__ __forceinline__ float rna_tf32(float x) {
    uint32_t r; asm("cvt.rna.tf32.f32 %0, %1;" : "=r"(r) : "f"(x));
    return __uint_as_float(r);
}

#define CPASYNC16(saddr, gaddr) \
    asm volatile("cp.async.cg.shared.global [%0], [%1], 16;" :: "r"(saddr), "l"(gaddr))

__device__ __forceinline__ void ldm4(uint32_t* r, uint32_t addr) {
    asm volatile("ldmatrix.sync.aligned.m8n8.x4.shared.b16 {%0,%1,%2,%3}, [%4];"
                 : "=r"(r[0]), "=r"(r[1]), "=r"(r[2]), "=r"(r[3]) : "r"(addr));
}
__device__ __forceinline__ void mma8(float* c, const uint32_t* a, const uint32_t* b) {
    asm volatile(
        "mma.sync.aligned.m16n8k8.row.col.f32.tf32.tf32.f32 "
        "{%0,%1,%2,%3}, {%4,%5,%6,%7}, {%8,%9}, {%0,%1,%2,%3};"
        : "+f"(c[0]), "+f"(c[1]), "+f"(c[2]), "+f"(c[3])
        : "r"(a[0]), "r"(a[1]), "r"(a[2]), "r"(a[3]), "r"(b[0]), "r"(b[1]));
}
__device__ __forceinline__ void mma16(float* c, const uint32_t* a, const uint32_t* b) {
    asm volatile(
        "mma.sync.aligned.m16n8k16.row.col.f32.bf16.bf16.f32 "
        "{%0,%1,%2,%3}, {%4,%5,%6,%7}, {%8,%9}, {%0,%1,%2,%3};"
        : "+f"(c[0]), "+f"(c[1]), "+f"(c[2]), "+f"(c[3])
        : "r"(a[0]), "r"(a[1]), "r"(a[2]), "r"(a[3]), "r"(b[0]), "r"(b[1]));
}

struct SegArgs  { const float* a[3];          const float* b[3];          };
struct SegArgsB { const __nv_bfloat16* a[3];  const __nv_bfloat16* b[3];  };

static const int NSTG = 3;                       // 3 stages -> 2 CTAs/SM
static const int STAGE = 32768;                  // 16KB A + 16KB B
static const int GEMM_SMEM = 1024 + NSTG * STAGE;

// ---------------------------------------------------------------------------
// tf32 GEMM: C[M,N] = sum_seg A_seg[M,1024] * B_seg[N,1024]^T
// EPI: 1 round-to-tf32, 2 tanh(x+bias)
// ---------------------------------------------------------------------------
template <int EPI, int NSEG>
__global__ __launch_bounds__(256, 2)
void gemm_mma(const SegArgs segs, float* __restrict__ C,
              const float* __restrict__ bias, int ldb, int ldc,
              long long sA, long long sB, long long sC)
{
    extern __shared__ char smem[];
    const uint32_t data = (smem_u32(smem) + 1023) & ~1023u;

    const int tid  = threadIdx.x;
    const int lane = tid & 31;
    const int warp = tid >> 5;
    const int wm = (warp >> 2) << 6;
    const int wn = (warp & 3) << 5;
    const int bm = blockIdx.y << 7;
    const int bn = blockIdx.x << 7;

    const long long zA = (long long)blockIdx.z * sA;
    const long long zB = (long long)blockIdx.z * sB;
    float* Cb = C + (size_t)blockIdx.z * sC;

    const int KT = NSEG * 32;

    auto fill = [&](int kt, int s) {
        const int seg = kt >> 5;
        const int ka  = (kt & 31) << 5;
        const float* Ap = segs.a[seg] + zA;
        const float* Bp = segs.b[seg] + zB;
        const uint32_t sa = data + s * STAGE;
        const uint32_t sb = sa + 16384;
#pragma unroll
        for (int i = 0; i < 4; i++) {
            int c = tid + (i << 8);
            int row = c >> 3, ch = c & 7;
            const float* g = Ap + (size_t)(bm + row) * 1024 + ka + (ch << 2);
            CPASYNC16(sa + (row << 7) + (((ch ^ (row & 7))) << 4), g);
        }
#pragma unroll
        for (int i = 0; i < 4; i++) {
            int c = tid + (i << 8);
            int row = c >> 3, ch = c & 7;
            const float* g = Bp + (size_t)(bn + row) * ldb + ka + (ch << 2);
            CPASYNC16(sb + (row << 7) + (((ch ^ (row & 7))) << 4), g);
        }
    };

    fill(0, 0);
    asm volatile("cp.async.commit_group;" ::: "memory");
    fill(1, 1);
    asm volatile("cp.async.commit_group;" ::: "memory");

    float acc[4][4][4];
#pragma unroll
    for (int a = 0; a < 4; a++)
#pragma unroll
        for (int b = 0; b < 4; b++)
#pragma unroll
            for (int c = 0; c < 4; c++) acc[a][b][c] = 0.f;

    const int r8 = lane & 7;
    const int mh = lane >> 3;

    int sc = 0;                                  // stage of current kt
    for (int kt = 0; kt < KT; kt++) {
        asm volatile("cp.async.wait_group 1;" ::: "memory");
        __syncthreads();

        int nf = kt + 2;
        int fs = (sc == 0) ? 2 : sc - 1;         // (sc+2) % 3
        if (nf < KT) fill(nf, fs);
        asm volatile("cp.async.commit_group;" ::: "memory");

        const uint32_t Ab = data + sc * STAGE;
        const uint32_t Bs = Ab + 16384;
#pragma unroll
        for (int k8 = 0; k8 < 4; k8++) {
            uint32_t af[4][4], bf[2][4];
#pragma unroll
            for (int mt = 0; mt < 4; mt++) {
                int arow = wm + mt * 16 + r8 + ((mh & 1) << 3);
                int achk = 2 * k8 + (mh >> 1);
                ldm4(af[mt], Ab + (arow << 7) + (((achk ^ (arow & 7))) << 4));
            }
#pragma unroll
            for (int p = 0; p < 2; p++) {
                int brow = wn + (p << 4) + r8 + ((mh >> 1) << 3);
                int bchk = 2 * k8 + (mh & 1);
                ldm4(bf[p], Bs + (brow << 7) + (((bchk ^ (brow & 7))) << 4));
            }
#pragma unroll
            for (int mt = 0; mt < 4; mt++)
#pragma unroll
                for (int nt = 0; nt < 4; nt++)
                    mma8(acc[mt][nt], af[mt], &bf[nt >> 1][(nt & 1) << 1]);
        }
        sc = (sc == 2) ? 0 : sc + 1;
    }

    const int row0 = bm + wm + (lane >> 2);
    const int col0 = bn + wn + ((lane & 3) << 1);
#pragma unroll
    for (int mt = 0; mt < 4; mt++) {
#pragma unroll
        for (int nt = 0; nt < 4; nt++) {
            int col = col0 + nt * 8;
#pragma unroll
            for (int h = 0; h < 2; h++) {
                int row = row0 + mt * 16 + h * 8;
                float v0 = acc[mt][nt][2 * h + 0];
                float v1 = acc[mt][nt][2 * h + 1];
                float* dst = Cb + (size_t)row * ldc + col;
                if (EPI == 1) {
                    float2 o = {rna_tf32(v0), rna_tf32(v1)};
                    *(float2*)dst = o;
                } else {  // EPI == 2
                    float2 o = {tanhf(v0 + bias[col]), tanhf(v1 + bias[col + 1])};
                    *(float2*)dst = o;
                }
            }
        }
    }
}

// ---------------------------------------------------------------------------
// bf16 GEMM: C[M,N] = sum_seg A_seg[M,1024] * B_seg[N,1024]^T  (bf16, fp32 acc)
// k-step 64 elements per stage. EPI: 0 fp32 out, 4 split->bh,bl
// ---------------------------------------------------------------------------
template <int EPI, int NSEG>
__global__ __launch_bounds__(256, 2)
void gemm_bf16(const SegArgsB segs, float* __restrict__ Cf,
               __nv_bfloat16* __restrict__ Chi, __nv_bfloat16* __restrict__ Clo,
               int ldb, int ldc, long long sA, long long sB, long long sC)
{
    extern __shared__ char smem[];
    const uint32_t data = (smem_u32(smem) + 1023) & ~1023u;

    const int tid  = threadIdx.x;
    const int lane = tid & 31;
    const int warp = tid >> 5;
    const int wm = (warp >> 2) << 6;
    const int wn = (warp & 3) << 5;
    const int bm = blockIdx.y << 7;
    const int bn = blockIdx.x << 7;

    const long long zA = (long long)blockIdx.z * sA;
    const long long zB = (long long)blockIdx.z * sB;

    const int KT = NSEG * 16;            // k-steps of 64 bf16

    auto fill = [&](int kt, int s) {
        const int seg = kt >> 4;
        const int ka  = (kt & 15) << 6;
        const __nv_bfloat16* Ap = segs.a[seg] + zA;
        const __nv_bfloat16* Bp = segs.b[seg] + zB;
        const uint32_t sa = data + s * STAGE;
        const uint32_t sb = sa + 16384;
#pragma unroll
        for (int i = 0; i < 4; i++) {
            int c = tid + (i << 8);
            int row = c >> 3, ch = c & 7;
            const __nv_bfloat16* g = Ap + (size_t)(bm + row) * 1024 + ka + (ch << 3);
            CPASYNC16(sa + (row << 7) + (((ch ^ (row & 7))) << 4), g);
        }
#pragma unroll
        for (int i = 0; i < 4; i++) {
            int c = tid + (i << 8);
            int row = c >> 3, ch = c & 7;
            const __nv_bfloat16* g = Bp + (size_t)(bn + row) * ldb + ka + (ch << 3);
            CPASYNC16(sb + (row << 7) + (((ch ^ (row & 7))) << 4), g);
        }
    };

    fill(0, 0);
    asm volatile("cp.async.commit_group;" ::: "memory");
    fill(1, 1);
    asm volatile("cp.async.commit_group;" ::: "memory");

    float acc[4][4][4];
#pragma unroll
    for (int a = 0; a < 4; a++)
#pragma unroll
        for (int b = 0; b < 4; b++)
#pragma unroll
            for (int c = 0; c < 4; c++) acc[a][b][c] = 0.f;

    const int r8   = lane & 7;
    const int tile = lane >> 3;
    const int amo  = (tile & 1) << 3;
    const int akc  = tile >> 1;
    const int bno  = (lane >> 4) << 3;
    const int bkc  = (lane >> 3) & 1;

    int sc = 0;
    for (int kt = 0; kt < KT; kt++) {
        asm volatile("cp.async.wait_group 1;" ::: "memory");
        __syncthreads();

        int nf = kt + 2;
        int fs = (sc == 0) ? 2 : sc - 1;
        if (nf < KT) fill(nf, fs);
        asm volatile("cp.async.commit_group;" ::: "memory");

        const uint32_t Ab = data + sc * STAGE;
        const uint32_t Bs = Ab + 16384;
#pragma unroll
        for (int k16 = 0; k16 < 4; k16++) {
            uint32_t af[4][4], bf[2][4];
#pragma unroll
            for (int mt = 0; mt < 4; mt++) {
                int arow = wm + mt * 16 + r8 + amo;
                int achk = 2 * k16 + akc;
                ldm4(af[mt], Ab + (arow << 7) + (((achk ^ (arow & 7))) << 4));
            }
#pragma unroll
            for (int p = 0; p < 2; p++) {
                int brow = wn + (p << 4) + r8 + bno;
                int bchk = 2 * k16 + bkc;
                ldm4(bf[p], Bs + (brow << 7) + (((bchk ^ (brow & 7))) << 4));
            }
#pragma unroll
            for (int mt = 0; mt < 4; mt++)
#pragma unroll
                for (int nt = 0; nt < 4; nt++)
                    mma16(acc[mt][nt], af[mt], &bf[nt >> 1][(nt & 1) << 1]);
        }
        sc = (sc == 2) ? 0 : sc + 1;
    }

    const int row0 = bm + wm + (lane >> 2);
    const int col0 = bn + wn + ((lane & 3) << 1);
#pragma unroll
    for (int mt = 0; mt < 4; mt++) {
#pragma unroll
        for (int nt = 0; nt < 4; nt++) {
            int col = col0 + nt * 8;
#pragma unroll
            for (int h = 0; h < 2; h++) {
                int row = row0 + mt * 16 + h * 8;
                float v0 = acc[mt][nt][2 * h + 0];
                float v1 = acc[mt][nt][2 * h + 1];
                if (EPI == 0) {
                    float* dst = Cf + (size_t)blockIdx.z * sC + (size_t)row * ldc + col;
                    float2 o = {v0, v1};
                    *(float2*)dst = o;
                } else {  // EPI == 4: split to bf16 pairs
                    __nv_bfloat16 h0 = __float2bfloat16_rn(v0);
                    __nv_bfloat16 h1 = __float2bfloat16_rn(v1);
                    __nv_bfloat162 hv; hv.x = h0; hv.y = h1;
                    __nv_bfloat162 lv;
                    lv.x = __float2bfloat16_rn(v0 - __bfloat162float(h0));
                    lv.y = __float2bfloat16_rn(v1 - __bfloat162float(h1));
                    size_t off = (size_t)blockIdx.z * sC + (size_t)row * ldc + col;
                    *(__nv_bfloat162*)(Chi + off) = hv;
                    *(__nv_bfloat162*)(Clo + off) = lv;
                }
            }
        }
    }
}

// ---------------------------------------------------------------------------
// Preprocessing (merged)
// ---------------------------------------------------------------------------
// ht combo: ht -> ht_bh, ht_bl, ht_hi (all row-major, one pass)
__global__ void prep_ht(const float* __restrict__ in, __nv_bfloat16* __restrict__ bh,
                        __nv_bfloat16* __restrict__ bl, float* __restrict__ hi,
                        size_t n4)
{
    size_t i  = (size_t)blockIdx.x * blockDim.x + threadIdx.x;
    size_t st = (size_t)gridDim.x * blockDim.x;
    for (; i < n4; i += st) {
        float4 v = ((const float4*)in)[i];
        __nv_bfloat162 h0, h1, l0, l1;
        h0.x = __float2bfloat16_rn(v.x); l0.x = __float2bfloat16_rn(v.x - __bfloat162float(h0.x));
        h0.y = __float2bfloat16_rn(v.y); l0.y = __float2bfloat16_rn(v.y - __bfloat162float(h0.y));
        h1.x = __float2bfloat16_rn(v.z); l1.x = __float2bfloat16_rn(v.z - __bfloat162float(h1.x));
        h1.y = __float2bfloat16_rn(v.w); l1.y = __float2bfloat16_rn(v.w - __bfloat162float(h1.y));
        ((__nv_bfloat162*)bh)[2 * i]     = h0;
        ((__nv_bfloat162*)bh)[2 * i + 1] = h1;
        ((__nv_bfloat162*)bl)[2 * i]     = l0;
        ((__nv_bfloat162*)bl)[2 * i + 1] = l1;
        float4 t = {rna_tf32(v.x), rna_tf32(v.y), rna_tf32(v.z), rna_tf32(v.w)};
        ((float4*)hi)[i] = t;
    }
}

// hs combo: hs -> hs_bh, hs_bl (row-major) + hsT_hi (transposed tf32)
__global__ void prep_hs(const float* __restrict__ src, __nv_bfloat16* __restrict__ bh,
                        __nv_bfloat16* __restrict__ bl, float* __restrict__ tdst,
                        int R, int C)
{
    __shared__ float t[32][33];
    size_t boff = (size_t)blockIdx.z * R * C;
    src += boff; tdst += boff;
    bh += boff; bl += boff;
    int r0 = blockIdx.y << 5, c0 = blockIdx.x << 5;
    int tx = threadIdx.x, ty = threadIdx.y;
#pragma unroll
    for (int i = 0; i < 32; i += 8) {
        float v = src[(size_t)(r0 + ty + i) * C + c0 + tx];
        t[ty + i][tx] = v;
        __nv_bfloat16 h = __float2bfloat16_rn(v);
        size_t idx = (size_t)(r0 + ty + i) * C + c0 + tx;
        bh[idx] = h;
        bl[idx] = __float2bfloat16_rn(v - __bfloat162float(h));
    }
    __syncthreads();
#pragma unroll
    for (int i = 0; i < 32; i += 8)
        tdst[(size_t)(c0 + ty + i) * R + r0 + tx] = rna_tf32(t[tx][ty + i]);
}

// dst[c][r] = round_tf32(src[r][c])
__global__ void transpose_round(const float* __restrict__ src, float* __restrict__ dst,
                                int R, int C)
{
    __shared__ float t[32][33];
    int r0 = blockIdx.y << 5, c0 = blockIdx.x << 5;
    int tx = threadIdx.x, ty = threadIdx.y;
#pragma unroll
    for (int i = 0; i < 32; i += 8)
        t[ty + i][tx] = src[(size_t)(r0 + ty + i) * C + c0 + tx];
    __syncthreads();
#pragma unroll
    for (int i = 0; i < 32; i += 8)
        dst[(size_t)(c0 + ty + i) * R + r0 + tx] = rna_tf32(t[tx][ty + i]);
}

// dst_{bh,bl}[c][r] = bf16-split(src[r][c])
__global__ void transpose_split_bf16(const float* __restrict__ src,
                                     __nv_bfloat16* __restrict__ hi,
                                     __nv_bfloat16* __restrict__ lo, int R, int C)
{
    __shared__ float t[32][33];
    int r0 = blockIdx.y << 5, c0 = blockIdx.x << 5;
    int tx = threadIdx.x, ty = threadIdx.y;
#pragma unroll
    for (int i = 0; i < 32; i += 8)
        t[ty + i][tx] = src[(size_t)(r0 + ty + i) * C + c0 + tx];
    __syncthreads();
#pragma unroll
    for (int i = 0; i < 32; i += 8) {
        float v = t[tx][ty + i];
        __nv_bfloat16 h = __float2bfloat16_rn(v);
        __nv_bfloat16 l = __float2bfloat16_rn(v - __bfloat162float(h));
        size_t idx = (size_t)(c0 + ty + i) * R + r0 + tx;
        hi[idx] = h;
        lo[idx] = l;
    }
}

__global__ void lens_kernel(const int* __restrict__ source, int* __restrict__ lens)
{
    int b = blockIdx.x, tid = threadIdx.x;
    int cnt = 0;
    for (int s = tid; s < TS; s += blockDim.x)
        cnt += (source[(size_t)b * TS + s] != 0);
    __shared__ int red[256];
    red[tid] = cnt;
    __syncthreads();
    for (int s = 128; s > 0; s >>= 1) {
        if (tid < s) red[tid] += red[tid + s];
        __syncthreads();
    }
    if (tid == 0) lens[b] = red[0];
}

// masked softmax; writes a rounded to tf32, in-place
__global__ void softmax_kernel(float* __restrict__ score, const int* __restrict__ lens)
{
    int row = blockIdx.x;
    int b = row >> 10;
    int tid = threadIdx.x;
    float* r = score + (size_t)row * TS;
    int len = lens[b];

    float4 x = ((const float4*)r)[tid];
    float m = fmaxf(fmaxf(x.x, x.y), fmaxf(x.z, x.w));
    __shared__ float red[256];
    red[tid] = m;
    __syncthreads();
    for (int s = 128; s > 0; s >>= 1) {
        if (tid < s) red[tid] = fmaxf(red[tid], red[tid + s]);
        __syncthreads();
    }
    float rowmax = red[0];
    __syncthreads();

    int base = tid * 4;
    float e0 = (base + 0 < len) ? expf(x.x - rowmax) : 0.f;
    float e1 = (base + 1 < len) ? expf(x.y - rowmax) : 0.f;
    float e2 = (base + 2 < len) ? expf(x.z - rowmax) : 0.f;
    float e3 = (base + 3 < len) ? expf(x.w - rowmax) : 0.f;

    red[tid] = e0 + e1 + e2 + e3;
    __syncthreads();
    for (int s = 128; s > 0; s >>= 1) {
        if (tid < s) red[tid] += red[tid + s];
        __syncthreads();
    }
    float inv = 1.0f / red[0];

    float4 o = {rna_tf32(e0 * inv), rna_tf32(e1 * inv),
                rna_tf32(e2 * inv), rna_tf32(e3 * inv)};
    ((float4*)r)[tid] = o;
}

// ---------------------------------------------------------------------------
// Host launch
// ---------------------------------------------------------------------------
extern "C" void kernel_launch(void* const* d_in, const int* in_sizes, int n_in,
                              void* d_out, int out_size)
{
    const float* ht     = (const float*)d_in[0];
    const float* hs     = (const float*)d_in[1];
    const float* W_a    = (const float*)d_in[2];
    const float* W_c    = (const float*)d_in[3];
    const float* bias   = (const float*)d_in[4];
    const int*   source = (const int*)d_in[5];
    float* out = (float*)d_out;

    __nv_bfloat16 *hs_bh, *hs_bl, *ht_bh, *ht_bl, *WaT_bh, *WaT_bl, *proj_bh, *proj_bl;
    float *score, *hsT_hi, *c, *ht_hi, *WcT_hi;
    int* lens;
    cudaGetSymbolAddress((void**)&hs_bh,   g_hs_bh);
    cudaGetSymbolAddress((void**)&hs_bl,   g_hs_bl);
    cudaGetSymbolAddress((void**)&ht_bh,   g_ht_bh);
    cudaGetSymbolAddress((void**)&ht_bl,   g_ht_bl);
    cudaGetSymbolAddress((void**)&WaT_bh,  g_WaT_bh);
    cudaGetSymbolAddress((void**)&WaT_bl,  g_WaT_bl);
    cudaGetSymbolAddress((void**)&proj_bh, g_proj_bh);
    cudaGetSymbolAddress((void**)&proj_bl, g_proj_bl);
    cudaGetSymbolAddress((void**)&score,   g_score);
    cudaGetSymbolAddress((void**)&hsT_hi,  g_hsT_hi);
    cudaGetSymbolAddress((void**)&c,       g_c);
    cudaGetSymbolAddress((void**)&ht_hi,   g_ht_hi);
    cudaGetSymbolAddress((void**)&WcT_hi,  g_WcT_hi);
    cudaGetSymbolAddress((void**)&lens,    g_lens);

    cudaFuncSetAttribute(gemm_bf16<4,3>, cudaFuncAttributeMaxDynamicSharedMemorySize, GEMM_SMEM);
    cudaFuncSetAttribute(gemm_bf16<0,3>, cudaFuncAttributeMaxDynamicSharedMemorySize, GEMM_SMEM);
    cudaFuncSetAttribute(gemm_mma<1,1>,  cudaFuncAttributeMaxDynamicSharedMemorySize, GEMM_SMEM);
    cudaFuncSetAttribute(gemm_mma<2,2>,  cudaFuncAttributeMaxDynamicSharedMemorySize, GEMM_SMEM);

    // Preprocess (ordered so G1 is the 6th launch -> ncu -s 5 -c 1 captures it)
    lens_kernel<<<NB, 256>>>(source, lens);                                    // 1
    prep_ht<<<2048, 256>>>(ht, ht_bh, ht_bl, ht_hi, (size_t)NB * TT * HH / 4); // 2
    transpose_split_bf16<<<dim3(32, 32), dim3(32, 8)>>>(W_a, WaT_bh, WaT_bl, HH, HH); // 3
    transpose_round<<<dim3(32, 64), dim3(32, 8)>>>(W_c, WcT_hi, 2 * HH, OO);   // 4
    prep_hs<<<dim3(32, 32, NB), dim3(32, 8)>>>(hs, hs_bh, hs_bl, hsT_hi, TS, HH); // 5

    // G1: proj = hs @ W_a  (3xBF16), EPI=split -> proj_bh, proj_bl           // 6
    {
        SegArgsB s{};
        s.a[0] = hs_bh;  s.a[1] = hs_bl;  s.a[2] = hs_bh;
        s.b[0] = WaT_bh; s.b[1] = WaT_bh; s.b[2] = WaT_bl;
        gemm_bf16<4,3><<<dim3(HH/128, NB*TS/128, 1), 256, GEMM_SMEM>>>(
            s, nullptr, proj_bh, proj_bl, 1024, HH, 0, 0, (long long)0);
    }

    // G2: score[b] = ht[b] @ proj[b]^T  (3xBF16), batched, EPI=plain fp32
    {
        SegArgsB s{};
        s.a[0] = ht_bh;   s.a[1] = ht_bl;   s.a[2] = ht_bh;
        s.b[0] = proj_bh; s.b[1] = proj_bh; s.b[2] = proj_bl;
        gemm_bf16<0,3><<<dim3(TS/128, TT/128, NB), 256, GEMM_SMEM>>>(
            s, score, nullptr, nullptr, 1024, TS,
            (long long)TT * HH, (long long)TS * HH, (long long)TT * TS);
    }

    // masked softmax -> a (tf32-rounded, in score)
    softmax_kernel<<<NB * TT, 256>>>(score, lens);

    // G3: c[b] = a[b] @ hs[b]  (single tf32), EPI=round -> c
    {
        SegArgs s{};
        s.a[0] = score;
        s.b[0] = hsT_hi;
        gemm_mma<1,1><<<dim3(HH/128, TT/128, NB), 256, GEMM_SMEM>>>(
            s, c, nullptr, 1024, HH,
            (long long)TT * TS, (long long)HH * TS, (long long)TT * HH);
    }

    // G4: out = tanh([c|ht] @ W_c + b)  (single tf32, 2 segments over K=2048)
    {
        SegArgs s{};
        s.a[0] = c;      s.a[1] = ht_hi;
        s.b[0] = WcT_hi; s.b[1] = WcT_hi + 1024;
        gemm_mma<2,2><<<dim3(OO/128, NB*TT/128, 1), 256, GEMM_SMEM>>>(
            s, out, bias, 2048, OO, 0, 0, 0);
    }
}

// round 8
// speedup vs baseline: 5.5726x; 1.2995x over previous
#include <cuda_runtime.h>
#include <cuda_fp16.h>
#include <math.h>
#include <cstdint>

// Problem shape (fixed)
#define NB 16
#define TT 1024
#define TS 1024
#define HH 1024
#define OO 1024

// ---------------------------------------------------------------------------
// Scratch (device globals; no allocation). _h/_l = exact fp16 hi/lo pairs.
// ---------------------------------------------------------------------------
__device__ __half g_hs_h  [(size_t)NB * TS * HH];
__device__ __half g_hs_l  [(size_t)NB * TS * HH];
__device__ __half g_ht_h  [(size_t)NB * TT * HH];
__device__ __half g_ht_l  [(size_t)NB * TT * HH];
__device__ __half g_WaT_h [(size_t)HH * HH];        // scaled by 32
__device__ __half g_WaT_l [(size_t)HH * HH];        // scaled by 32
__device__ __half g_proj_h[(size_t)NB * TS * HH];
__device__ __half g_proj_l[(size_t)NB * TS * HH];
__device__ __half g_a_h   [(size_t)NB * TT * TS];   // softmax weights fp16
__device__ __half g_hsT_h [(size_t)NB * HH * TS];   // hs^T fp16
__device__ __half g_c_h   [(size_t)NB * TT * HH];   // c fp16
__device__ __half g_WcT_h [(size_t)OO * 2 * HH];    // [O=1024][K=2048] fp16
__device__ float  g_score [(size_t)NB * TT * TS];   // raw scores fp32
__device__ int    g_lens  [NB];

// ---------------------------------------------------------------------------
// Helpers / PTX (base ISA only)
// ---------------------------------------------------------------------------
__device__ __forceinline__ uint32_t smem_u32(const void* p) {
    uint32_t a;
    asm("{ .reg .u64 t; cvta.to.shared.u64 t, %1; cvt.u32.u64 %0, t; }"
        : "=r"(a) : "l"(p));
    return a;
}

#define CPASYNC16(saddr, gaddr) \
    asm volatile("cp.async.cg.shared.global [%0], [%1], 16;" :: "r"(saddr), "l"(gaddr))

__device__ __forceinline__ void ldm4(uint32_t* r, uint32_t addr) {
    asm volatile("ldmatrix.sync.aligned.m8n8.x4.shared.b16 {%0,%1,%2,%3}, [%4];"
                 : "=r"(r[0]), "=r"(r[1]), "=r"(r[2]), "=r"(r[3]) : "r"(addr));
}
__device__ __forceinline__ void mma16h(float* c, const uint32_t* a, const uint32_t* b) {
    asm volatile(
        "mma.sync.aligned.m16n8k16.row.col.f32.f16.f16.f32 "
        "{%0,%1,%2,%3}, {%4,%5,%6,%7}, {%8,%9}, {%0,%1,%2,%3};"
        : "+f"(c[0]), "+f"(c[1]), "+f"(c[2]), "+f"(c[3])
        : "r"(a[0]), "r"(a[1]), "r"(a[2]), "r"(a[3]), "r"(b[0]), "r"(b[1]));
}

struct SegArgsH { const __half* a[3]; const __half* b[3]; };

static const int NSTG = 3;                       // 3 stages -> 2 CTAs/SM
static const int STAGE = 32768;                  // 16KB A + 16KB B
static const int GEMM_SMEM = 1024 + NSTG * STAGE;

// ---------------------------------------------------------------------------
// fp16 GEMM: C[M,N] = sum_seg A_seg[M,1024] * B_seg[N,1024]^T (fp16 in, fp32 acc)
// CTA tile 128x128, k-step 64, 8 warps (2x4) with 64x32 warp tiles,
// 3-stage cp.async pipeline, SW128 xor swizzle, ldmatrix fragments.
// EPI: 0 fp32 out, 1 fp16 split out (scaled), 2 tanh(x+bias) fp32, 3 fp16 out
// ---------------------------------------------------------------------------
template <int EPI, int NSEG>
__global__ __launch_bounds__(256, 2)
void gemm_fp16(const SegArgsH segs, float* __restrict__ Cf,
               __half* __restrict__ Ch, __half* __restrict__ Ch2,
               const float* __restrict__ bias, float oscale,
               int ldb, int ldc, long long sA, long long sB, long long sC)
{
    extern __shared__ char smem[];
    const uint32_t data = (smem_u32(smem) + 1023) & ~1023u;

    const int tid  = threadIdx.x;
    const int lane = tid & 31;
    const int warp = tid >> 5;
    const int wm = (warp >> 2) << 6;
    const int wn = (warp & 3) << 5;
    const int bm = blockIdx.y << 7;
    const int bn = blockIdx.x << 7;

    const long long zA = (long long)blockIdx.z * sA;
    const long long zB = (long long)blockIdx.z * sB;

    const int KT = NSEG * 16;            // k-steps of 64 fp16

    auto fill = [&](int kt, int s) {
        const int seg = kt >> 4;
        const int ka  = (kt & 15) << 6;
        const __half* Ap = segs.a[seg] + zA;
        const __half* Bp = segs.b[seg] + zB;
        const uint32_t sa = data + s * STAGE;
        const uint32_t sb = sa + 16384;
#pragma unroll
        for (int i = 0; i < 4; i++) {
            int c = tid + (i << 8);
            int row = c >> 3, ch = c & 7;
            const __half* g = Ap + (size_t)(bm + row) * 1024 + ka + (ch << 3);
            CPASYNC16(sa + (row << 7) + (((ch ^ (row & 7))) << 4), g);
        }
#pragma unroll
        for (int i = 0; i < 4; i++) {
            int c = tid + (i << 8);
            int row = c >> 3, ch = c & 7;
            const __half* g = Bp + (size_t)(bn + row) * ldb + ka + (ch << 3);
            CPASYNC16(sb + (row << 7) + (((ch ^ (row & 7))) << 4), g);
        }
    };

    fill(0, 0);
    asm volatile("cp.async.commit_group;" ::: "memory");
    fill(1, 1);
    asm volatile("cp.async.commit_group;" ::: "memory");

    float acc[4][4][4];
#pragma unroll
    for (int a = 0; a < 4; a++)
#pragma unroll
        for (int b = 0; b < 4; b++)
#pragma unroll
            for (int c = 0; c < 4; c++) acc[a][b][c] = 0.f;

    const int r8   = lane & 7;
    const int tile = lane >> 3;
    const int amo  = (tile & 1) << 3;
    const int akc  = tile >> 1;
    const int bno  = (lane >> 4) << 3;
    const int bkc  = (lane >> 3) & 1;

    int sc = 0;
    for (int kt = 0; kt < KT; kt++) {
        asm volatile("cp.async.wait_group 1;" ::: "memory");
        __syncthreads();

        int nf = kt + 2;
        int fs = (sc == 0) ? 2 : sc - 1;
        if (nf < KT) fill(nf, fs);
        asm volatile("cp.async.commit_group;" ::: "memory");

        const uint32_t Ab = data + sc * STAGE;
        const uint32_t Bs = Ab + 16384;
#pragma unroll
        for (int k16 = 0; k16 < 4; k16++) {
            uint32_t af[4][4], bf[2][4];
#pragma unroll
            for (int mt = 0; mt < 4; mt++) {
                int arow = wm + mt * 16 + r8 + amo;
                int achk = 2 * k16 + akc;
                ldm4(af[mt], Ab + (arow << 7) + (((achk ^ (arow & 7))) << 4));
            }
#pragma unroll
            for (int p = 0; p < 2; p++) {
                int brow = wn + (p << 4) + r8 + bno;
                int bchk = 2 * k16 + bkc;
                ldm4(bf[p], Bs + (brow << 7) + (((bchk ^ (brow & 7))) << 4));
            }
#pragma unroll
            for (int mt = 0; mt < 4; mt++)
#pragma unroll
                for (int nt = 0; nt < 4; nt++)
                    mma16h(acc[mt][nt], af[mt], &bf[nt >> 1][(nt & 1) << 1]);
        }
        sc = (sc == 2) ? 0 : sc + 1;
    }

    const int row0 = bm + wm + (lane >> 2);
    const int col0 = bn + wn + ((lane & 3) << 1);
#pragma unroll
    for (int mt = 0; mt < 4; mt++) {
#pragma unroll
        for (int nt = 0; nt < 4; nt++) {
            int col = col0 + nt * 8;
#pragma unroll
            for (int h = 0; h < 2; h++) {
                int row = row0 + mt * 16 + h * 8;
                float v0 = acc[mt][nt][2 * h + 0];
                float v1 = acc[mt][nt][2 * h + 1];
                size_t off = (size_t)blockIdx.z * sC + (size_t)row * ldc + col;
                if (EPI == 0) {
                    float2 o = {v0, v1};
                    *(float2*)(Cf + off) = o;
                } else if (EPI == 1) {          // scaled fp16 split
                    v0 *= oscale; v1 *= oscale;
                    __half h0 = __float2half_rn(v0);
                    __half h1 = __float2half_rn(v1);
                    __half2 hv; hv.x = h0; hv.y = h1;
                    __half2 lv;
                    lv.x = __float2half_rn(v0 - __half2float(h0));
                    lv.y = __float2half_rn(v1 - __half2float(h1));
                    *(__half2*)(Ch + off)  = hv;
                    *(__half2*)(Ch2 + off) = lv;
                } else if (EPI == 2) {          // tanh + bias
                    float2 o = {tanhf(v0 + bias[col]), tanhf(v1 + bias[col + 1])};
                    *(float2*)(Cf + off) = o;
                } else {                        // EPI == 3: fp16 single
                    __half2 hv;
                    hv.x = __float2half_rn(v0);
                    hv.y = __float2half_rn(v1);
                    *(__half2*)(Ch + off) = hv;
                }
            }
        }
    }
}

// ---------------------------------------------------------------------------
// Preprocessing
// ---------------------------------------------------------------------------
// x -> fp16 hi/lo pairs (row-major), one pass
__global__ void prep_split(const float* __restrict__ in, __half* __restrict__ hh,
                           __half* __restrict__ hl, size_t n4)
{
    size_t i  = (size_t)blockIdx.x * blockDim.x + threadIdx.x;
    size_t st = (size_t)gridDim.x * blockDim.x;
    for (; i < n4; i += st) {
        float4 v = ((const float4*)in)[i];
        __half2 h0, h1, l0, l1;
        h0.x = __float2half_rn(v.x); l0.x = __float2half_rn(v.x - __half2float(h0.x));
        h0.y = __float2half_rn(v.y); l0.y = __float2half_rn(v.y - __half2float(h0.y));
        h1.x = __float2half_rn(v.z); l1.x = __float2half_rn(v.z - __half2float(h1.x));
        h1.y = __float2half_rn(v.w); l1.y = __float2half_rn(v.w - __half2float(h1.y));
        ((__half2*)hh)[2 * i]     = h0;
        ((__half2*)hh)[2 * i + 1] = h1;
        ((__half2*)hl)[2 * i]     = l0;
        ((__half2*)hl)[2 * i + 1] = l1;
    }
}

// hs combo: hs -> hs_h, hs_l (row-major) + hsT_h (transposed fp16)
__global__ void prep_hs(const float* __restrict__ src, __half* __restrict__ hh,
                        __half* __restrict__ hl, __half* __restrict__ tdst,
                        int R, int C)
{
    __shared__ float t[32][33];
    size_t boff = (size_t)blockIdx.z * R * C;
    src += boff; tdst += boff;
    hh += boff; hl += boff;
    int r0 = blockIdx.y << 5, c0 = blockIdx.x << 5;
    int tx = threadIdx.x, ty = threadIdx.y;
#pragma unroll
    for (int i = 0; i < 32; i += 8) {
        float v = src[(size_t)(r0 + ty + i) * C + c0 + tx];
        t[ty + i][tx] = v;
        __half h = __float2half_rn(v);
        size_t idx = (size_t)(r0 + ty + i) * C + c0 + tx;
        hh[idx] = h;
        hl[idx] = __float2half_rn(v - __half2float(h));
    }
    __syncthreads();
#pragma unroll
    for (int i = 0; i < 32; i += 8)
        tdst[(size_t)(c0 + ty + i) * R + r0 + tx] = __float2half_rn(t[tx][ty + i]);
}

// Wa: dst_{h,l}[c][r] = fp16-split(32 * src[r][c])   (scale keeps lo normal)
__global__ void prep_wa(const float* __restrict__ src, __half* __restrict__ hh,
                        __half* __restrict__ hl, int R, int C)
{
    __shared__ float t[32][33];
    int r0 = blockIdx.y << 5, c0 = blockIdx.x << 5;
    int tx = threadIdx.x, ty = threadIdx.y;
#pragma unroll
    for (int i = 0; i < 32; i += 8)
        t[ty + i][tx] = src[(size_t)(r0 + ty + i) * C + c0 + tx];
    __syncthreads();
#pragma unroll
    for (int i = 0; i < 32; i += 8) {
        float v = 32.0f * t[tx][ty + i];
        __half h = __float2half_rn(v);
        __half l = __float2half_rn(v - __half2float(h));
        size_t idx = (size_t)(c0 + ty + i) * R + r0 + tx;
        hh[idx] = h;
        hl[idx] = l;
    }
}

// Wc: dst[c][r] = fp16(src[r][c])
__global__ void prep_wc(const float* __restrict__ src, __half* __restrict__ dst,
                        int R, int C)
{
    __shared__ float t[32][33];
    int r0 = blockIdx.y << 5, c0 = blockIdx.x << 5;
    int tx = threadIdx.x, ty = threadIdx.y;
#pragma unroll
    for (int i = 0; i < 32; i += 8)
        t[ty + i][tx] = src[(size_t)(r0 + ty + i) * C + c0 + tx];
    __syncthreads();
#pragma unroll
    for (int i = 0; i < 32; i += 8)
        dst[(size_t)(c0 + ty + i) * R + r0 + tx] = __float2half_rn(t[tx][ty + i]);
}

__global__ void lens_kernel(const int* __restrict__ source, int* __restrict__ lens)
{
    int b = blockIdx.x, tid = threadIdx.x;
    int cnt = 0;
    for (int s = tid; s < TS; s += blockDim.x)
        cnt += (source[(size_t)b * TS + s] != 0);
    __shared__ int red[256];
    red[tid] = cnt;
    __syncthreads();
    for (int s = 128; s > 0; s >>= 1) {
        if (tid < s) red[tid] += red[tid + s];
        __syncthreads();
    }
    if (tid == 0) lens[b] = red[0];
}

// masked softmax, warp-per-row (no block barriers); writes fp16 a
__global__ void softmax_kernel(const float* __restrict__ score,
                               __half* __restrict__ a_h,
                               const int* __restrict__ lens)
{
    int warp = threadIdx.x >> 5;
    int lane = threadIdx.x & 31;
    int row  = (blockIdx.x << 3) + warp;         // 8 warps/block
    int b    = row >> 10;
    const float* r = score + (size_t)row * TS;
    __half* ar = a_h + (size_t)row * TS;
    int len = lens[b];

    float4 x[8];
    float m = -1e30f;
#pragma unroll
    for (int i = 0; i < 8; i++) {
        x[i] = ((const float4*)r)[lane + (i << 5)];
        m = fmaxf(m, fmaxf(fmaxf(x[i].x, x[i].y), fmaxf(x[i].z, x[i].w)));
    }
#pragma unroll
    for (int s = 16; s > 0; s >>= 1)
        m = fmaxf(m, __shfl_xor_sync(0xffffffffu, m, s));

    float e[8][4];
    float sum = 0.f;
#pragma unroll
    for (int i = 0; i < 8; i++) {
        int base = (lane + (i << 5)) << 2;
        e[i][0] = (base + 0 < len) ? expf(x[i].x - m) : 0.f;
        e[i][1] = (base + 1 < len) ? expf(x[i].y - m) : 0.f;
        e[i][2] = (base + 2 < len) ? expf(x[i].z - m) : 0.f;
        e[i][3] = (base + 3 < len) ? expf(x[i].w - m) : 0.f;
        sum += e[i][0] + e[i][1] + e[i][2] + e[i][3];
    }
#pragma unroll
    for (int s = 16; s > 0; s >>= 1)
        sum += __shfl_xor_sync(0xffffffffu, sum, s);
    float inv = 1.0f / sum;

#pragma unroll
    for (int i = 0; i < 8; i++) {
        int idx = lane + (i << 5);
        __half2 o0, o1;
        o0.x = __float2half_rn(e[i][0] * inv);
        o0.y = __float2half_rn(e[i][1] * inv);
        o1.x = __float2half_rn(e[i][2] * inv);
        o1.y = __float2half_rn(e[i][3] * inv);
        ((__half2*)ar)[2 * idx]     = o0;
        ((__half2*)ar)[2 * idx + 1] = o1;
    }
}

// ---------------------------------------------------------------------------
// Host launch
// ---------------------------------------------------------------------------
extern "C" void kernel_launch(void* const* d_in, const int* in_sizes, int n_in,
                              void* d_out, int out_size)
{
    const float* ht     = (const float*)d_in[0];
    const float* hs     = (const float*)d_in[1];
    const float* W_a    = (const float*)d_in[2];
    const float* W_c    = (const float*)d_in[3];
    const float* bias   = (const float*)d_in[4];
    const int*   source = (const int*)d_in[5];
    float* out = (float*)d_out;

    __half *hs_h, *hs_l, *ht_h, *ht_l, *WaT_h, *WaT_l, *proj_h, *proj_l;
    __half *a_h, *hsT_h, *c_h, *WcT_h;
    float* score;
    int* lens;
    cudaGetSymbolAddress((void**)&hs_h,   g_hs_h);
    cudaGetSymbolAddress((void**)&hs_l,   g_hs_l);
    cudaGetSymbolAddress((void**)&ht_h,   g_ht_h);
    cudaGetSymbolAddress((void**)&ht_l,   g_ht_l);
    cudaGetSymbolAddress((void**)&WaT_h,  g_WaT_h);
    cudaGetSymbolAddress((void**)&WaT_l,  g_WaT_l);
    cudaGetSymbolAddress((void**)&proj_h, g_proj_h);
    cudaGetSymbolAddress((void**)&proj_l, g_proj_l);
    cudaGetSymbolAddress((void**)&a_h,    g_a_h);
    cudaGetSymbolAddress((void**)&hsT_h,  g_hsT_h);
    cudaGetSymbolAddress((void**)&c_h,    g_c_h);
    cudaGetSymbolAddress((void**)&WcT_h,  g_WcT_h);
    cudaGetSymbolAddress((void**)&score,  g_score);
    cudaGetSymbolAddress((void**)&lens,   g_lens);

    cudaFuncSetAttribute(gemm_fp16<1,3>, cudaFuncAttributeMaxDynamicSharedMemorySize, GEMM_SMEM);
    cudaFuncSetAttribute(gemm_fp16<0,3>, cudaFuncAttributeMaxDynamicSharedMemorySize, GEMM_SMEM);
    cudaFuncSetAttribute(gemm_fp16<3,1>, cudaFuncAttributeMaxDynamicSharedMemorySize, GEMM_SMEM);
    cudaFuncSetAttribute(gemm_fp16<2,2>, cudaFuncAttributeMaxDynamicSharedMemorySize, GEMM_SMEM);

    // Preprocess
    lens_kernel<<<NB, 256>>>(source, lens);
    prep_split<<<2048, 256>>>(ht, ht_h, ht_l, (size_t)NB * TT * HH / 4);
    prep_wa<<<dim3(32, 32), dim3(32, 8)>>>(W_a, WaT_h, WaT_l, HH, HH);
    prep_wc<<<dim3(32, 64), dim3(32, 8)>>>(W_c, WcT_h, 2 * HH, OO);
    prep_hs<<<dim3(32, 32, NB), dim3(32, 8)>>>(hs, hs_h, hs_l, hsT_h, TS, HH);

    // G1: proj = hs @ W_a  (3xFP16, Wa scaled by 32) -> proj_h, proj_l (x 1/32)
    {
        SegArgsH s{};
        s.a[0] = hs_h;  s.a[1] = hs_l;  s.a[2] = hs_h;
        s.b[0] = WaT_h; s.b[1] = WaT_h; s.b[2] = WaT_l;
        gemm_fp16<1,3><<<dim3(HH/128, NB*TS/128, 1), 256, GEMM_SMEM>>>(
            s, nullptr, proj_h, proj_l, nullptr, 1.0f / 32.0f,
            1024, HH, 0, 0, (long long)TT * HH);
    }

    // G2: score[b] = ht[b] @ proj[b]^T  (3xFP16), fp32 out
    {
        SegArgsH s{};
        s.a[0] = ht_h;   s.a[1] = ht_l;   s.a[2] = ht_h;
        s.b[0] = proj_h; s.b[1] = proj_h; s.b[2] = proj_l;
        gemm_fp16<0,3><<<dim3(TS/128, TT/128, NB), 256, GEMM_SMEM>>>(
            s, score, nullptr, nullptr, nullptr, 1.0f,
            1024, TS, (long long)TT * HH, (long long)TS * HH, (long long)TT * TS);
    }

    // masked softmax -> a_h (fp16)
    softmax_kernel<<<NB * TT / 8, 256>>>(score, a_h, lens);

    // G3: c[b] = a[b] @ hs[b]  (single fp16) -> c_h
    {
        SegArgsH s{};
        s.a[0] = a_h;
        s.b[0] = hsT_h;
        gemm_fp16<3,1><<<dim3(HH/128, TT/128, NB), 256, GEMM_SMEM>>>(
            s, nullptr, c_h, nullptr, nullptr, 1.0f,
            1024, HH, (long long)TT * TS, (long long)HH * TS, (long long)TT * HH);
    }

    // G4: out = tanh([c|ht] @ W_c + b)  (single fp16, 2 segments over K=2048)
    {
        SegArgsH s{};
        s.a[0] = c_h;   s.a[1] = ht_h;
        s.b[0] = WcT_h; s.b[1] = WcT_h + 1024;
        gemm_fp16<2,2><<<dim3(OO/128, NB*TT/128, 1), 256, GEMM_SMEM>>>(
            s, out, nullptr, nullptr, bias, 1.0f,
            2048, OO, 0, 0, 0);
    }
}

// round 9
// speedup vs baseline: 5.8768x; 1.0546x over previous
#include <cuda_runtime.h>
#include <cuda_fp16.h>
#include <math.h>
#include <cstdint>

// Problem shape (fixed)
#define NB 16
#define TT 1024
#define TS 1024
#define HH 1024
#define OO 1024

// ---------------------------------------------------------------------------
// Scratch (device globals; no allocation). _h/_l = exact fp16 hi/lo pairs.
// ---------------------------------------------------------------------------
__device__ __half g_hs_h  [(size_t)NB * TS * HH];
__device__ __half g_hs_l  [(size_t)NB * TS * HH];
__device__ __half g_ht_h  [(size_t)NB * TT * HH];
__device__ __half g_ht_l  [(size_t)NB * TT * HH];
__device__ __half g_WaT_h [(size_t)HH * HH];        // scaled by 32
__device__ __half g_WaT_l [(size_t)HH * HH];        // scaled by 32
__device__ __half g_proj_h[(size_t)NB * TS * HH];
__device__ __half g_proj_l[(size_t)NB * TS * HH];
__device__ __half g_c_h   [(size_t)NB * TT * HH];   // c fp16 (from sparse AV)
__device__ __half g_WcT_h [(size_t)OO * 2 * HH];    // [O=1024][K=2048] fp16
__device__ float  g_score [(size_t)NB * TT * TS];   // raw scores fp32
__device__ int    g_sidx  [(size_t)NB * TT * TS];   // sparse a: indices
__device__ float  g_sval  [(size_t)NB * TT * TS];   // sparse a: fp32 values
__device__ int    g_scnt  [NB * TT];                // sparse a: counts
__device__ int    g_lens  [NB];

// ---------------------------------------------------------------------------
// Helpers / PTX (base ISA only)
// ---------------------------------------------------------------------------
__device__ __forceinline__ uint32_t smem_u32(const void* p) {
    uint32_t a;
    asm("{ .reg .u64 t; cvta.to.shared.u64 t, %1; cvt.u32.u64 %0, t; }"
        : "=r"(a) : "l"(p));
    return a;
}

#define CPASYNC16(saddr, gaddr) \
    asm volatile("cp.async.cg.shared.global [%0], [%1], 16;" :: "r"(saddr), "l"(gaddr))

__device__ __forceinline__ void ldm4(uint32_t* r, uint32_t addr) {
    asm volatile("ldmatrix.sync.aligned.m8n8.x4.shared.b16 {%0,%1,%2,%3}, [%4];"
                 : "=r"(r[0]), "=r"(r[1]), "=r"(r[2]), "=r"(r[3]) : "r"(addr));
}
__device__ __forceinline__ void mma16h(float* c, const uint32_t* a, const uint32_t* b) {
    asm volatile(
        "mma.sync.aligned.m16n8k16.row.col.f32.f16.f16.f32 "
        "{%0,%1,%2,%3}, {%4,%5,%6,%7}, {%8,%9}, {%0,%1,%2,%3};"
        : "+f"(c[0]), "+f"(c[1]), "+f"(c[2]), "+f"(c[3])
        : "r"(a[0]), "r"(a[1]), "r"(a[2]), "r"(a[3]), "r"(b[0]), "r"(b[1]));
}

struct SegArgsH { const __half* a[3]; const __half* b[3]; };

static const int NSTG = 3;                       // 3 stages -> 2 CTAs/SM
static const int STAGE = 32768;                  // 16KB A + 16KB B
static const int GEMM_SMEM = 1024 + NSTG * STAGE;

// ---------------------------------------------------------------------------
// fp16 GEMM: C[M,N] = sum_seg A_seg[M,1024] * B_seg[N,1024]^T (fp16 in, fp32 acc)
// CTA tile 128x128, k-step 64, 8 warps (2x4) with 64x32 warp tiles,
// 3-stage cp.async pipeline, SW128 xor swizzle, ldmatrix fragments.
// EPI: 0 fp32 out, 1 fp16 split out (scaled), 2 tanh(x+bias) fp32
// ---------------------------------------------------------------------------
template <int EPI, int NSEG>
__global__ __launch_bounds__(256, 2)
void gemm_fp16(const SegArgsH segs, float* __restrict__ Cf,
               __half* __restrict__ Ch, __half* __restrict__ Ch2,
               const float* __restrict__ bias, float oscale,
               int ldb, int ldc, long long sA, long long sB, long long sC)
{
    extern __shared__ char smem[];
    const uint32_t data = (smem_u32(smem) + 1023) & ~1023u;

    const int tid  = threadIdx.x;
    const int lane = tid & 31;
    const int warp = tid >> 5;
    const int wm = (warp >> 2) << 6;
    const int wn = (warp & 3) << 5;
    const int bm = blockIdx.y << 7;
    const int bn = blockIdx.x << 7;

    const long long zA = (long long)blockIdx.z * sA;
    const long long zB = (long long)blockIdx.z * sB;

    const int KT = NSEG * 16;            // k-steps of 64 fp16

    auto fill = [&](int kt, int s) {
        const int seg = kt >> 4;
        const int ka  = (kt & 15) << 6;
        const __half* Ap = segs.a[seg] + zA;
        const __half* Bp = segs.b[seg] + zB;
        const uint32_t sa = data + s * STAGE;
        const uint32_t sb = sa + 16384;
#pragma unroll
        for (int i = 0; i < 4; i++) {
            int c = tid + (i << 8);
            int row = c >> 3, ch = c & 7;
            const __half* g = Ap + (size_t)(bm + row) * 1024 + ka + (ch << 3);
            CPASYNC16(sa + (row << 7) + (((ch ^ (row & 7))) << 4), g);
        }
#pragma unroll
        for (int i = 0; i < 4; i++) {
            int c = tid + (i << 8);
            int row = c >> 3, ch = c & 7;
            const __half* g = Bp + (size_t)(bn + row) * ldb + ka + (ch << 3);
            CPASYNC16(sb + (row << 7) + (((ch ^ (row & 7))) << 4), g);
        }
    };

    fill(0, 0);
    asm volatile("cp.async.commit_group;" ::: "memory");
    fill(1, 1);
    asm volatile("cp.async.commit_group;" ::: "memory");

    float acc[4][4][4];
#pragma unroll
    for (int a = 0; a < 4; a++)
#pragma unroll
        for (int b = 0; b < 4; b++)
#pragma unroll
            for (int c = 0; c < 4; c++) acc[a][b][c] = 0.f;

    const int r8   = lane & 7;
    const int tile = lane >> 3;
    const int amo  = (tile & 1) << 3;
    const int akc  = tile >> 1;
    const int bno  = (lane >> 4) << 3;
    const int bkc  = (lane >> 3) & 1;

    int sc = 0;
    for (int kt = 0; kt < KT; kt++) {
        asm volatile("cp.async.wait_group 1;" ::: "memory");
        __syncthreads();

        int nf = kt + 2;
        int fs = (sc == 0) ? 2 : sc - 1;
        if (nf < KT) fill(nf, fs);
        asm volatile("cp.async.commit_group;" ::: "memory");

        const uint32_t Ab = data + sc * STAGE;
        const uint32_t Bs = Ab + 16384;
#pragma unroll
        for (int k16 = 0; k16 < 4; k16++) {
            uint32_t af[4][4], bf[2][4];
#pragma unroll
            for (int mt = 0; mt < 4; mt++) {
                int arow = wm + mt * 16 + r8 + amo;
                int achk = 2 * k16 + akc;
                ldm4(af[mt], Ab + (arow << 7) + (((achk ^ (arow & 7))) << 4));
            }
#pragma unroll
            for (int p = 0; p < 2; p++) {
                int brow = wn + (p << 4) + r8 + bno;
                int bchk = 2 * k16 + bkc;
                ldm4(bf[p], Bs + (brow << 7) + (((bchk ^ (brow & 7))) << 4));
            }
#pragma unroll
            for (int mt = 0; mt < 4; mt++)
#pragma unroll
                for (int nt = 0; nt < 4; nt++)
                    mma16h(acc[mt][nt], af[mt], &bf[nt >> 1][(nt & 1) << 1]);
        }
        sc = (sc == 2) ? 0 : sc + 1;
    }

    const int row0 = bm + wm + (lane >> 2);
    const int col0 = bn + wn + ((lane & 3) << 1);
#pragma unroll
    for (int mt = 0; mt < 4; mt++) {
#pragma unroll
        for (int nt = 0; nt < 4; nt++) {
            int col = col0 + nt * 8;
#pragma unroll
            for (int h = 0; h < 2; h++) {
                int row = row0 + mt * 16 + h * 8;
                float v0 = acc[mt][nt][2 * h + 0];
                float v1 = acc[mt][nt][2 * h + 1];
                size_t off = (size_t)blockIdx.z * sC + (size_t)row * ldc + col;
                if (EPI == 0) {
                    float2 o = {v0, v1};
                    *(float2*)(Cf + off) = o;
                } else if (EPI == 1) {          // scaled fp16 split
                    v0 *= oscale; v1 *= oscale;
                    __half h0 = __float2half_rn(v0);
                    __half h1 = __float2half_rn(v1);
                    __half2 hv; hv.x = h0; hv.y = h1;
                    __half2 lv;
                    lv.x = __float2half_rn(v0 - __half2float(h0));
                    lv.y = __float2half_rn(v1 - __half2float(h1));
                    *(__half2*)(Ch + off)  = hv;
                    *(__half2*)(Ch2 + off) = lv;
                } else {                        // EPI == 2: tanh + bias
                    float2 o = {tanhf(v0 + bias[col]), tanhf(v1 + bias[col + 1])};
                    *(float2*)(Cf + off) = o;
                }
            }
        }
    }
}

// ---------------------------------------------------------------------------
// Preprocessing
// ---------------------------------------------------------------------------
// x -> fp16 hi/lo pairs (row-major), one pass
__global__ void prep_split(const float* __restrict__ in, __half* __restrict__ hh,
                           __half* __restrict__ hl, size_t n4)
{
    size_t i  = (size_t)blockIdx.x * blockDim.x + threadIdx.x;
    size_t st = (size_t)gridDim.x * blockDim.x;
    for (; i < n4; i += st) {
        float4 v = ((const float4*)in)[i];
        __half2 h0, h1, l0, l1;
        h0.x = __float2half_rn(v.x); l0.x = __float2half_rn(v.x - __half2float(h0.x));
        h0.y = __float2half_rn(v.y); l0.y = __float2half_rn(v.y - __half2float(h0.y));
        h1.x = __float2half_rn(v.z); l1.x = __float2half_rn(v.z - __half2float(h1.x));
        h1.y = __float2half_rn(v.w); l1.y = __float2half_rn(v.w - __half2float(h1.y));
        ((__half2*)hh)[2 * i]     = h0;
        ((__half2*)hh)[2 * i + 1] = h1;
        ((__half2*)hl)[2 * i]     = l0;
        ((__half2*)hl)[2 * i + 1] = l1;
    }
}

// Merged weight prep: blockIdx.y < 32 -> Wa (fp16 split, scaled 32, transpose);
// else -> Wc (fp16 single, transpose). One launch.
__global__ void prep_w(const float* __restrict__ Wa, const float* __restrict__ Wc,
                       __half* __restrict__ WaT_h, __half* __restrict__ WaT_l,
                       __half* __restrict__ WcT_h)
{
    __shared__ float t[32][33];
    int y = blockIdx.y;
    bool isWa = (y < 32);
    const float* src = isWa ? Wa : Wc;
    int r0 = (isWa ? y : (y - 32)) << 5;
    int c0 = blockIdx.x << 5;
    int tx = threadIdx.x, ty = threadIdx.y;
#pragma unroll
    for (int i = 0; i < 32; i += 8)
        t[ty + i][tx] = src[(size_t)(r0 + ty + i) * 1024 + c0 + tx];
    __syncthreads();
    if (isWa) {
#pragma unroll
        for (int i = 0; i < 32; i += 8) {
            float v = 32.0f * t[tx][ty + i];
            __half h = __float2half_rn(v);
            __half l = __float2half_rn(v - __half2float(h));
            size_t idx = (size_t)(c0 + ty + i) * 1024 + r0 + tx;
            WaT_h[idx] = h;
            WaT_l[idx] = l;
        }
    } else {
#pragma unroll
        for (int i = 0; i < 32; i += 8) {
            size_t idx = (size_t)(c0 + ty + i) * 2048 + r0 + tx;
            WcT_h[idx] = __float2half_rn(t[tx][ty + i]);
        }
    }
}

__global__ void lens_kernel(const int* __restrict__ source, int* __restrict__ lens)
{
    int b = blockIdx.x, tid = threadIdx.x;
    int cnt = 0;
    for (int s = tid; s < TS; s += blockDim.x)
        cnt += (source[(size_t)b * TS + s] != 0);
    __shared__ int red[256];
    red[tid] = cnt;
    __syncthreads();
    for (int s = 128; s > 0; s >>= 1) {
        if (tid < s) red[tid] += red[tid + s];
        __syncthreads();
    }
    if (tid == 0) lens[b] = red[0];
}

// masked softmax, warp-per-row; emits compact sparse list (a >= 2^-25, fp32)
__global__ void softmax_sparse(const float* __restrict__ score,
                               int* __restrict__ sidx, float* __restrict__ sval,
                               int* __restrict__ scnt,
                               const int* __restrict__ lens)
{
    int warp = threadIdx.x >> 5;
    int lane = threadIdx.x & 31;
    int row  = (blockIdx.x << 3) + warp;         // 8 warps/block
    int b    = row >> 10;
    const float* r = score + (size_t)row * TS;
    int len = lens[b];

    float4 x[8];
    float m = -1e30f;
#pragma unroll
    for (int i = 0; i < 8; i++) {
        x[i] = ((const float4*)r)[lane + (i << 5)];
        m = fmaxf(m, fmaxf(fmaxf(x[i].x, x[i].y), fmaxf(x[i].z, x[i].w)));
    }
#pragma unroll
    for (int s = 16; s > 0; s >>= 1)
        m = fmaxf(m, __shfl_xor_sync(0xffffffffu, m, s));

    float e[8][4];
    float sum = 0.f;
#pragma unroll
    for (int i = 0; i < 8; i++) {
        int base = (lane + (i << 5)) << 2;
        e[i][0] = (base + 0 < len) ? expf(x[i].x - m) : 0.f;
        e[i][1] = (base + 1 < len) ? expf(x[i].y - m) : 0.f;
        e[i][2] = (base + 2 < len) ? expf(x[i].z - m) : 0.f;
        e[i][3] = (base + 3 < len) ? expf(x[i].w - m) : 0.f;
        sum += e[i][0] + e[i][1] + e[i][2] + e[i][3];
    }
#pragma unroll
    for (int s = 16; s > 0; s >>= 1)
        sum += __shfl_xor_sync(0xffffffffu, sum, s);
    float inv = 1.0f / sum;
    float thr = 2.9802322387695312e-8f * sum;    // a >= 2^-25 (matches fp16 cutoff)

    int* si = sidx + (size_t)row * TS;
    float* sv = sval + (size_t)row * TS;
    int base = 0;
#pragma unroll
    for (int i = 0; i < 8; i++) {
        int sb = (lane + (i << 5)) << 2;
#pragma unroll
        for (int j = 0; j < 4; j++) {
            bool p = e[i][j] >= thr;
            unsigned mask = __ballot_sync(0xffffffffu, p);
            if (p) {
                int pos = base + __popc(mask & ((1u << lane) - 1));
                si[pos] = sb + j;
                sv[pos] = e[i][j] * inv;
            }
            base += __popc(mask);
        }
    }
    if (lane == 0) scnt[row] = base;
}

// sparse A*V: c[row,:] = sum_k sval_k * hs[b, sidx_k, :]  -> fp16
__global__ __launch_bounds__(256)
void sparse_av(const float* __restrict__ hs, const int* __restrict__ sidx,
               const float* __restrict__ sval, const int* __restrict__ scnt,
               __half* __restrict__ c_h)
{
    int row = blockIdx.x;                        // 0 .. NB*TT-1
    int b = row >> 10;
    int tid = threadIdx.x;
    int K = scnt[row];
    const int* si = sidx + (size_t)row * TS;
    const float* sv = sval + (size_t)row * TS;

    float4 acc = {0.f, 0.f, 0.f, 0.f};
    for (int k = 0; k < K; k++) {
        int s = si[k];
        float v = sv[k];
        float4 h = ((const float4*)(hs + ((size_t)b * TS + s) * HH))[tid];
        acc.x += v * h.x; acc.y += v * h.y;
        acc.z += v * h.z; acc.w += v * h.w;
    }
    __half2 o0, o1;
    o0.x = __float2half_rn(acc.x); o0.y = __float2half_rn(acc.y);
    o1.x = __float2half_rn(acc.z); o1.y = __float2half_rn(acc.w);
    ((__half2*)(c_h + (size_t)row * HH))[2 * tid]     = o0;
    ((__half2*)(c_h + (size_t)row * HH))[2 * tid + 1] = o1;
}

// ---------------------------------------------------------------------------
// Host launch
// ---------------------------------------------------------------------------
extern "C" void kernel_launch(void* const* d_in, const int* in_sizes, int n_in,
                              void* d_out, int out_size)
{
    const float* ht     = (const float*)d_in[0];
    const float* hs     = (const float*)d_in[1];
    const float* W_a    = (const float*)d_in[2];
    const float* W_c    = (const float*)d_in[3];
    const float* bias   = (const float*)d_in[4];
    const int*   source = (const int*)d_in[5];
    float* out = (float*)d_out;

    __half *hs_h, *hs_l, *ht_h, *ht_l, *WaT_h, *WaT_l, *proj_h, *proj_l, *c_h, *WcT_h;
    float *score, *sval;
    int *sidx, *scnt, *lens;
    cudaGetSymbolAddress((void**)&hs_h,   g_hs_h);
    cudaGetSymbolAddress((void**)&hs_l,   g_hs_l);
    cudaGetSymbolAddress((void**)&ht_h,   g_ht_h);
    cudaGetSymbolAddress((void**)&ht_l,   g_ht_l);
    cudaGetSymbolAddress((void**)&WaT_h,  g_WaT_h);
    cudaGetSymbolAddress((void**)&WaT_l,  g_WaT_l);
    cudaGetSymbolAddress((void**)&proj_h, g_proj_h);
    cudaGetSymbolAddress((void**)&proj_l, g_proj_l);
    cudaGetSymbolAddress((void**)&c_h,    g_c_h);
    cudaGetSymbolAddress((void**)&WcT_h,  g_WcT_h);
    cudaGetSymbolAddress((void**)&score,  g_score);
    cudaGetSymbolAddress((void**)&sidx,   g_sidx);
    cudaGetSymbolAddress((void**)&sval,   g_sval);
    cudaGetSymbolAddress((void**)&scnt,   g_scnt);
    cudaGetSymbolAddress((void**)&lens,   g_lens);

    cudaFuncSetAttribute(gemm_fp16<1,3>, cudaFuncAttributeMaxDynamicSharedMemorySize, GEMM_SMEM);
    cudaFuncSetAttribute(gemm_fp16<0,3>, cudaFuncAttributeMaxDynamicSharedMemorySize, GEMM_SMEM);
    cudaFuncSetAttribute(gemm_fp16<2,2>, cudaFuncAttributeMaxDynamicSharedMemorySize, GEMM_SMEM);

    // Preprocess
    lens_kernel<<<NB, 256>>>(source, lens);
    prep_w<<<dim3(32, 96), dim3(32, 8)>>>(W_a, W_c, WaT_h, WaT_l, WcT_h);
    prep_split<<<2048, 256>>>(ht, ht_h, ht_l, (size_t)NB * TT * HH / 4);
    prep_split<<<2048, 256>>>(hs, hs_h, hs_l, (size_t)NB * TS * HH / 4);

    // G1: proj = hs @ W_a  (3xFP16, Wa scaled by 32) -> proj_h, proj_l (x 1/32)
    {
        SegArgsH s{};
        s.a[0] = hs_h;  s.a[1] = hs_l;  s.a[2] = hs_h;
        s.b[0] = WaT_h; s.b[1] = WaT_h; s.b[2] = WaT_l;
        gemm_fp16<1,3><<<dim3(HH/128, NB*TS/128, 1), 256, GEMM_SMEM>>>(
            s, nullptr, proj_h, proj_l, nullptr, 1.0f / 32.0f,
            1024, HH, 0, 0, (long long)TT * HH);
    }

    // G2: score[b] = ht[b] @ proj[b]^T  (3xFP16), fp32 out
    {
        SegArgsH s{};
        s.a[0] = ht_h;   s.a[1] = ht_l;   s.a[2] = ht_h;
        s.b[0] = proj_h; s.b[1] = proj_h; s.b[2] = proj_l;
        gemm_fp16<0,3><<<dim3(TS/128, TT/128, NB), 256, GEMM_SMEM>>>(
            s, score, nullptr, nullptr, nullptr, 1.0f,
            1024, TS, (long long)TT * HH, (long long)TS * HH, (long long)TT * TS);
    }

    // masked softmax -> compact sparse (idx, fp32 val) lists
    softmax_sparse<<<NB * TT / 8, 256>>>(score, sidx, sval, scnt, lens);

    // G3 (sparse): c[row,:] = sum_k a_k * hs[b, s_k, :]  -> c_h fp16
    sparse_av<<<NB * TT, 256>>>(hs, sidx, sval, scnt, c_h);

    // G4: out = tanh([c|ht] @ W_c + b)  (single fp16, 2 segments over K=2048)
    {
        SegArgsH s{};
        s.a[0] = c_h;   s.a[1] = ht_h;
        s.b[0] = WcT_h; s.b[1] = WcT_h + 1024;
        gemm_fp16<2,2><<<dim3(OO/128, NB*TT/128, 1), 256, GEMM_SMEM>>>(
            s, out, nullptr, nullptr, bias, 1.0f,
            2048, OO, 0, 0, 0);
    }
}

// round 10
// speedup vs baseline: 5.9232x; 1.0079x over previous
#include <cuda_runtime.h>
#include <cuda_fp16.h>
#include <math.h>
#include <cstdint>

// Problem shape (fixed)
#define NB 16
#define TT 1024
#define TS 1024
#define HH 1024
#define OO 1024

// ---------------------------------------------------------------------------
// Scratch (device globals; no allocation). _h/_l = exact fp16 hi/lo pairs.
// ---------------------------------------------------------------------------
__device__ __half g_hs_h  [(size_t)NB * TS * HH];
__device__ __half g_hs_l  [(size_t)NB * TS * HH];
__device__ __half g_ht_h  [(size_t)NB * TT * HH];
__device__ __half g_ht_l  [(size_t)NB * TT * HH];
__device__ __half g_WaT_h [(size_t)HH * HH];        // scaled by 32
__device__ __half g_WaT_l [(size_t)HH * HH];        // scaled by 32
__device__ __half g_proj_h[(size_t)NB * TS * HH];
__device__ __half g_proj_l[(size_t)NB * TS * HH];
__device__ __half g_c_h   [(size_t)NB * TT * HH];   // c fp16 (from sparse AV)
__device__ __half g_WcT_h [(size_t)OO * 2 * HH];    // [O=1024][K=2048] fp16
__device__ float  g_score [(size_t)NB * TT * TS];   // approx scores fp32
__device__ int    g_sidx  [(size_t)NB * TT * TS];   // sparse a: indices
__device__ float  g_sval  [(size_t)NB * TT * TS];   // sparse a: fp32 values
__device__ int    g_scnt  [NB * TT];                // sparse a: counts
__device__ int    g_lens  [NB];

// ---------------------------------------------------------------------------
// Helpers / PTX (base ISA only)
// ---------------------------------------------------------------------------
__device__ __forceinline__ uint32_t smem_u32(const void* p) {
    uint32_t a;
    asm("{ .reg .u64 t; cvta.to.shared.u64 t, %1; cvt.u32.u64 %0, t; }"
        : "=r"(a) : "l"(p));
    return a;
}

#define CPASYNC16(saddr, gaddr) \
    asm volatile("cp.async.cg.shared.global [%0], [%1], 16;" :: "r"(saddr), "l"(gaddr))

__device__ __forceinline__ void ldm4(uint32_t* r, uint32_t addr) {
    asm volatile("ldmatrix.sync.aligned.m8n8.x4.shared.b16 {%0,%1,%2,%3}, [%4];"
                 : "=r"(r[0]), "=r"(r[1]), "=r"(r[2]), "=r"(r[3]) : "r"(addr));
}
__device__ __forceinline__ void mma16h(float* c, const uint32_t* a, const uint32_t* b) {
    asm volatile(
        "mma.sync.aligned.m16n8k16.row.col.f32.f16.f16.f32 "
        "{%0,%1,%2,%3}, {%4,%5,%6,%7}, {%8,%9}, {%0,%1,%2,%3};"
        : "+f"(c[0]), "+f"(c[1]), "+f"(c[2]), "+f"(c[3])
        : "r"(a[0]), "r"(a[1]), "r"(a[2]), "r"(a[3]), "r"(b[0]), "r"(b[1]));
}

struct SegArgsH { const __half* a[3]; const __half* b[3]; };

static const int NSTG = 3;                       // 3 stages -> 2 CTAs/SM
static const int STAGE = 32768;                  // 16KB A + 16KB B
static const int GEMM_SMEM = 1024 + NSTG * STAGE;

// ---------------------------------------------------------------------------
// fp16 GEMM: C[M,N] = sum_seg A_seg[M,1024] * B_seg[N,1024]^T (fp16 in, fp32 acc)
// CTA tile 128x128, k-step 64, 8 warps (2x4) with 64x32 warp tiles,
// 3-stage cp.async pipeline, SW128 xor swizzle, ldmatrix fragments.
// EPI: 0 fp32 out, 1 fp16 split out (scaled), 2 tanh(x+bias) fp32
// ---------------------------------------------------------------------------
template <int EPI, int NSEG>
__global__ __launch_bounds__(256, 2)
void gemm_fp16(const SegArgsH segs, float* __restrict__ Cf,
               __half* __restrict__ Ch, __half* __restrict__ Ch2,
               const float* __restrict__ bias, float oscale,
               int ldb, int ldc, long long sA, long long sB, long long sC)
{
    extern __shared__ char smem[];
    const uint32_t data = (smem_u32(smem) + 1023) & ~1023u;

    const int tid  = threadIdx.x;
    const int lane = tid & 31;
    const int warp = tid >> 5;
    const int wm = (warp >> 2) << 6;
    const int wn = (warp & 3) << 5;
    const int bm = blockIdx.y << 7;
    const int bn = blockIdx.x << 7;

    const long long zA = (long long)blockIdx.z * sA;
    const long long zB = (long long)blockIdx.z * sB;

    const int KT = NSEG * 16;            // k-steps of 64 fp16

    auto fill = [&](int kt, int s) {
        const int seg = kt >> 4;
        const int ka  = (kt & 15) << 6;
        const __half* Ap = segs.a[seg] + zA;
        const __half* Bp = segs.b[seg] + zB;
        const uint32_t sa = data + s * STAGE;
        const uint32_t sb = sa + 16384;
#pragma unroll
        for (int i = 0; i < 4; i++) {
            int c = tid + (i << 8);
            int row = c >> 3, ch = c & 7;
            const __half* g = Ap + (size_t)(bm + row) * 1024 + ka + (ch << 3);
            CPASYNC16(sa + (row << 7) + (((ch ^ (row & 7))) << 4), g);
        }
#pragma unroll
        for (int i = 0; i < 4; i++) {
            int c = tid + (i << 8);
            int row = c >> 3, ch = c & 7;
            const __half* g = Bp + (size_t)(bn + row) * ldb + ka + (ch << 3);
            CPASYNC16(sb + (row << 7) + (((ch ^ (row & 7))) << 4), g);
        }
    };

    fill(0, 0);
    asm volatile("cp.async.commit_group;" ::: "memory");
    fill(1, 1);
    asm volatile("cp.async.commit_group;" ::: "memory");

    float acc[4][4][4];
#pragma unroll
    for (int a = 0; a < 4; a++)
#pragma unroll
        for (int b = 0; b < 4; b++)
#pragma unroll
            for (int c = 0; c < 4; c++) acc[a][b][c] = 0.f;

    const int r8   = lane & 7;
    const int tile = lane >> 3;
    const int amo  = (tile & 1) << 3;
    const int akc  = tile >> 1;
    const int bno  = (lane >> 4) << 3;
    const int bkc  = (lane >> 3) & 1;

    int sc = 0;
    for (int kt = 0; kt < KT; kt++) {
        asm volatile("cp.async.wait_group 1;" ::: "memory");
        __syncthreads();

        int nf = kt + 2;
        int fs = (sc == 0) ? 2 : sc - 1;
        if (nf < KT) fill(nf, fs);
        asm volatile("cp.async.commit_group;" ::: "memory");

        const uint32_t Ab = data + sc * STAGE;
        const uint32_t Bs = Ab + 16384;
#pragma unroll
        for (int k16 = 0; k16 < 4; k16++) {
            uint32_t af[4][4], bf[2][4];
#pragma unroll
            for (int mt = 0; mt < 4; mt++) {
                int arow = wm + mt * 16 + r8 + amo;
                int achk = 2 * k16 + akc;
                ldm4(af[mt], Ab + (arow << 7) + (((achk ^ (arow & 7))) << 4));
            }
#pragma unroll
            for (int p = 0; p < 2; p++) {
                int brow = wn + (p << 4) + r8 + bno;
                int bchk = 2 * k16 + bkc;
                ldm4(bf[p], Bs + (brow << 7) + (((bchk ^ (brow & 7))) << 4));
            }
#pragma unroll
            for (int mt = 0; mt < 4; mt++)
#pragma unroll
                for (int nt = 0; nt < 4; nt++)
                    mma16h(acc[mt][nt], af[mt], &bf[nt >> 1][(nt & 1) << 1]);
        }
        sc = (sc == 2) ? 0 : sc + 1;
    }

    const int row0 = bm + wm + (lane >> 2);
    const int col0 = bn + wn + ((lane & 3) << 1);
#pragma unroll
    for (int mt = 0; mt < 4; mt++) {
#pragma unroll
        for (int nt = 0; nt < 4; nt++) {
            int col = col0 + nt * 8;
#pragma unroll
            for (int h = 0; h < 2; h++) {
                int row = row0 + mt * 16 + h * 8;
                float v0 = acc[mt][nt][2 * h + 0];
                float v1 = acc[mt][nt][2 * h + 1];
                size_t off = (size_t)blockIdx.z * sC + (size_t)row * ldc + col;
                if (EPI == 0) {
                    float2 o = {v0, v1};
                    *(float2*)(Cf + off) = o;
                } else if (EPI == 1) {          // scaled fp16 split
                    v0 *= oscale; v1 *= oscale;
                    __half h0 = __float2half_rn(v0);
                    __half h1 = __float2half_rn(v1);
                    __half2 hv; hv.x = h0; hv.y = h1;
                    __half2 lv;
                    lv.x = __float2half_rn(v0 - __half2float(h0));
                    lv.y = __float2half_rn(v1 - __half2float(h1));
                    *(__half2*)(Ch + off)  = hv;
                    *(__half2*)(Ch2 + off) = lv;
                } else {                        // EPI == 2: tanh + bias
                    float2 o = {tanhf(v0 + bias[col]), tanhf(v1 + bias[col + 1])};
                    *(float2*)(Cf + off) = o;
                }
            }
        }
    }
}

// ---------------------------------------------------------------------------
// Preprocessing
// ---------------------------------------------------------------------------
__global__ void prep_split(const float* __restrict__ in, __half* __restrict__ hh,
                           __half* __restrict__ hl, size_t n4)
{
    size_t i  = (size_t)blockIdx.x * blockDim.x + threadIdx.x;
    size_t st = (size_t)gridDim.x * blockDim.x;
    for (; i < n4; i += st) {
        float4 v = ((const float4*)in)[i];
        __half2 h0, h1, l0, l1;
        h0.x = __float2half_rn(v.x); l0.x = __float2half_rn(v.x - __half2float(h0.x));
        h0.y = __float2half_rn(v.y); l0.y = __float2half_rn(v.y - __half2float(h0.y));
        h1.x = __float2half_rn(v.z); l1.x = __float2half_rn(v.z - __half2float(h1.x));
        h1.y = __float2half_rn(v.w); l1.y = __float2half_rn(v.w - __half2float(h1.y));
        ((__half2*)hh)[2 * i]     = h0;
        ((__half2*)hh)[2 * i + 1] = h1;
        ((__half2*)hl)[2 * i]     = l0;
        ((__half2*)hl)[2 * i + 1] = l1;
    }
}

// Merged weight prep: blockIdx.y < 32 -> Wa (fp16 split, scaled 32, transpose);
// else -> Wc (fp16 single, transpose).
__global__ void prep_w(const float* __restrict__ Wa, const float* __restrict__ Wc,
                       __half* __restrict__ WaT_h, __half* __restrict__ WaT_l,
                       __half* __restrict__ WcT_h)
{
    __shared__ float t[32][33];
    int y = blockIdx.y;
    bool isWa = (y < 32);
    const float* src = isWa ? Wa : Wc;
    int r0 = (isWa ? y : (y - 32)) << 5;
    int c0 = blockIdx.x << 5;
    int tx = threadIdx.x, ty = threadIdx.y;
#pragma unroll
    for (int i = 0; i < 32; i += 8)
        t[ty + i][tx] = src[(size_t)(r0 + ty + i) * 1024 + c0 + tx];
    __syncthreads();
    if (isWa) {
#pragma unroll
        for (int i = 0; i < 32; i += 8) {
            float v = 32.0f * t[tx][ty + i];
            __half h = __float2half_rn(v);
            __half l = __float2half_rn(v - __half2float(h));
            size_t idx = (size_t)(c0 + ty + i) * 1024 + r0 + tx;
            WaT_h[idx] = h;
            WaT_l[idx] = l;
        }
    } else {
#pragma unroll
        for (int i = 0; i < 32; i += 8) {
            size_t idx = (size_t)(c0 + ty + i) * 2048 + r0 + tx;
            WcT_h[idx] = __float2half_rn(t[tx][ty + i]);
        }
    }
}

__global__ void lens_kernel(const int* __restrict__ source, int* __restrict__ lens)
{
    int b = blockIdx.x, tid = threadIdx.x;
    int cnt = 0;
    for (int s = tid; s < TS; s += blockDim.x)
        cnt += (source[(size_t)b * TS + s] != 0);
    __shared__ int red[256];
    red[tid] = cnt;
    __syncthreads();
    for (int s = 128; s > 0; s >>= 1) {
        if (tid < s) red[tid] += red[tid + s];
        __syncthreads();
    }
    if (tid == 0) lens[b] = red[0];
}

// ---------------------------------------------------------------------------
// rescore: per row — select candidates from approx scores (margin-padded
// cutoff), recompute their scores exactly (fp32 ht . (proj_h+proj_l)),
// softmax over candidates -> sparse (idx, weight) list.
// ---------------------------------------------------------------------------
__global__ __launch_bounds__(256)
void rescore(const float* __restrict__ score, const float* __restrict__ ht,
             const __half* __restrict__ proj_h, const __half* __restrict__ proj_l,
             int* __restrict__ sidx, float* __restrict__ sval,
             int* __restrict__ scnt, const int* __restrict__ lens)
{
    __shared__ float htrow[1024];
    __shared__ int   cand[1024];
    __shared__ float exsc[1024];
    __shared__ float red[256];
    __shared__ int   ccnt;

    const int row = blockIdx.x;                   // 0 .. NB*TT-1
    const int b   = row >> 10;
    const int tid = threadIdx.x;
    const int len = lens[b];
    const float* srow = score + (size_t)row * TS;

    if (tid == 0) ccnt = 0;

    // load ht row (fp32 exact) into smem
    ((float4*)htrow)[tid] = ((const float4*)(ht + (size_t)row * HH))[tid];

    // masked max of approx scores
    float4 s4 = ((const float4*)srow)[tid];
    int base = tid << 2;
    float m = -1e30f;
    if (base + 0 < len) m = fmaxf(m, s4.x);
    if (base + 1 < len) m = fmaxf(m, s4.y);
    if (base + 2 < len) m = fmaxf(m, s4.z);
    if (base + 3 < len) m = fmaxf(m, s4.w);
    red[tid] = m;
    __syncthreads();
    for (int s = 128; s > 0; s >>= 1) {
        if (tid < s) red[tid] = fmaxf(red[tid], red[tid + s]);
        __syncthreads();
    }
    const float thr = red[0] - 18.2f;             // 17.33 cutoff + margin
    __syncthreads();

    // select candidates
    if (base + 0 < len && s4.x >= thr) cand[atomicAdd(&ccnt, 1)] = base + 0;
    if (base + 1 < len && s4.y >= thr) cand[atomicAdd(&ccnt, 1)] = base + 1;
    if (base + 2 < len && s4.z >= thr) cand[atomicAdd(&ccnt, 1)] = base + 2;
    if (base + 3 < len && s4.w >= thr) cand[atomicAdd(&ccnt, 1)] = base + 3;
    __syncthreads();
    const int C = ccnt;

    // exact rescore: warp per candidate
    const int warp = tid >> 5, lane = tid & 31;
    for (int ci = warp; ci < C; ci += 8) {
        int s = cand[ci];
        const __half* ph = proj_h + ((size_t)b * TS + s) * HH;
        const __half* pl = proj_l + ((size_t)b * TS + s) * HH;
        float acc = 0.f;
#pragma unroll
        for (int j = 0; j < 32; j++) {
            int k = lane + (j << 5);
            float p = __half2float(ph[k]) + __half2float(pl[k]);
            acc = fmaf(htrow[k], p, acc);
        }
#pragma unroll
        for (int s2 = 16; s2 > 0; s2 >>= 1)
            acc += __shfl_xor_sync(0xffffffffu, acc, s2);
        if (lane == 0) exsc[ci] = acc;
    }
    __syncthreads();

    // softmax over candidates (C is tiny)
    if (tid == 0) {
        float mx = -1e30f;
        for (int i = 0; i < C; i++) mx = fmaxf(mx, exsc[i]);
        float sum = 0.f;
        for (int i = 0; i < C; i++) {
            float e = expf(exsc[i] - mx);
            exsc[i] = e;
            sum += e;
        }
        red[0] = 1.0f / sum;
        scnt[row] = C;
    }
    __syncthreads();
    const float inv = red[0];
    for (int i = tid; i < C; i += 256) {
        sidx[(size_t)row * TS + i] = cand[i];
        sval[(size_t)row * TS + i] = exsc[i] * inv;
    }
}

// sparse A*V: c[row,:] = sum_k sval_k * hs[b, sidx_k, :]  -> fp16
__global__ __launch_bounds__(256)
void sparse_av(const float* __restrict__ hs, const int* __restrict__ sidx,
               const float* __restrict__ sval, const int* __restrict__ scnt,
               __half* __restrict__ c_h)
{
    int row = blockIdx.x;
    int b = row >> 10;
    int tid = threadIdx.x;
    int K = scnt[row];
    const int* si = sidx + (size_t)row * TS;
    const float* sv = sval + (size_t)row * TS;

    float4 acc = {0.f, 0.f, 0.f, 0.f};
    for (int k = 0; k < K; k++) {
        int s = si[k];
        float v = sv[k];
        float4 h = ((const float4*)(hs + ((size_t)b * TS + s) * HH))[tid];
        acc.x += v * h.x; acc.y += v * h.y;
        acc.z += v * h.z; acc.w += v * h.w;
    }
    __half2 o0, o1;
    o0.x = __float2half_rn(acc.x); o0.y = __float2half_rn(acc.y);
    o1.x = __float2half_rn(acc.z); o1.y = __float2half_rn(acc.w);
    ((__half2*)(c_h + (size_t)row * HH))[2 * tid]     = o0;
    ((__half2*)(c_h + (size_t)row * HH))[2 * tid + 1] = o1;
}

// ---------------------------------------------------------------------------
// Host launch
// ---------------------------------------------------------------------------
extern "C" void kernel_launch(void* const* d_in, const int* in_sizes, int n_in,
                              void* d_out, int out_size)
{
    const float* ht     = (const float*)d_in[0];
    const float* hs     = (const float*)d_in[1];
    const float* W_a    = (const float*)d_in[2];
    const float* W_c    = (const float*)d_in[3];
    const float* bias   = (const float*)d_in[4];
    const int*   source = (const int*)d_in[5];
    float* out = (float*)d_out;

    __half *hs_h, *hs_l, *ht_h, *ht_l, *WaT_h, *WaT_l, *proj_h, *proj_l, *c_h, *WcT_h;
    float *score, *sval;
    int *sidx, *scnt, *lens;
    cudaGetSymbolAddress((void**)&hs_h,   g_hs_h);
    cudaGetSymbolAddress((void**)&hs_l,   g_hs_l);
    cudaGetSymbolAddress((void**)&ht_h,   g_ht_h);
    cudaGetSymbolAddress((void**)&ht_l,   g_ht_l);
    cudaGetSymbolAddress((void**)&WaT_h,  g_WaT_h);
    cudaGetSymbolAddress((void**)&WaT_l,  g_WaT_l);
    cudaGetSymbolAddress((void**)&proj_h, g_proj_h);
    cudaGetSymbolAddress((void**)&proj_l, g_proj_l);
    cudaGetSymbolAddress((void**)&c_h,    g_c_h);
    cudaGetSymbolAddress((void**)&WcT_h,  g_WcT_h);
    cudaGetSymbolAddress((void**)&score,  g_score);
    cudaGetSymbolAddress((void**)&sidx,   g_sidx);
    cudaGetSymbolAddress((void**)&sval,   g_sval);
    cudaGetSymbolAddress((void**)&scnt,   g_scnt);
    cudaGetSymbolAddress((void**)&lens,   g_lens);

    cudaFuncSetAttribute(gemm_fp16<1,3>, cudaFuncAttributeMaxDynamicSharedMemorySize, GEMM_SMEM);
    cudaFuncSetAttribute(gemm_fp16<0,1>, cudaFuncAttributeMaxDynamicSharedMemorySize, GEMM_SMEM);
    cudaFuncSetAttribute(gemm_fp16<2,2>, cudaFuncAttributeMaxDynamicSharedMemorySize, GEMM_SMEM);

    // Preprocess
    lens_kernel<<<NB, 256>>>(source, lens);
    prep_w<<<dim3(32, 96), dim3(32, 8)>>>(W_a, W_c, WaT_h, WaT_l, WcT_h);
    prep_split<<<2048, 256>>>(ht, ht_h, ht_l, (size_t)NB * TT * HH / 4);
    prep_split<<<2048, 256>>>(hs, hs_h, hs_l, (size_t)NB * TS * HH / 4);

    // G1: proj = hs @ W_a  (3xFP16, Wa scaled by 32) -> proj_h, proj_l (x 1/32)
    {
        SegArgsH s{};
        s.a[0] = hs_h;  s.a[1] = hs_l;  s.a[2] = hs_h;
        s.b[0] = WaT_h; s.b[1] = WaT_h; s.b[2] = WaT_l;
        gemm_fp16<1,3><<<dim3(HH/128, NB*TS/128, 1), 256, GEMM_SMEM>>>(
            s, nullptr, proj_h, proj_l, nullptr, 1.0f / 32.0f,
            1024, HH, 0, 0, (long long)TT * HH);
    }

    // G2 (approx): score[b] = ht_h[b] @ proj_h[b]^T  (single fp16), fp32 out
    {
        SegArgsH s{};
        s.a[0] = ht_h;
        s.b[0] = proj_h;
        gemm_fp16<0,1><<<dim3(TS/128, TT/128, NB), 256, GEMM_SMEM>>>(
            s, score, nullptr, nullptr, nullptr, 1.0f,
            1024, TS, (long long)TT * HH, (long long)TS * HH, (long long)TT * TS);
    }

    // select + exact rescore + softmax -> sparse (idx, fp32 weight)
    rescore<<<NB * TT, 256>>>(score, ht, proj_h, proj_l, sidx, sval, scnt, lens);

    // G3 (sparse): c[row,:] = sum_k a_k * hs[b, s_k, :]  -> c_h fp16
    sparse_av<<<NB * TT, 256>>>(hs, sidx, sval, scnt, c_h);

    // G4: out = tanh([c|ht] @ W_c + b)  (single fp16, 2 segments over K=2048)
    {
        SegArgsH s{};
        s.a[0] = c_h;   s.a[1] = ht_h;
        s.b[0] = WcT_h; s.b[1] = WcT_h + 1024;
        gemm_fp16<2,2><<<dim3(OO/128, NB*TT/128, 1), 256, GEMM_SMEM>>>(
            s, out, nullptr, nullptr, bias, 1.0f,
            2048, OO, 0, 0, 0);
    }
}